// round 2
// baseline (speedup 1.0000x reference)
#include <cuda_runtime.h>
#include <cstdint>
#include <cstddef>

// ---------------------------------------------------------------------------
// Problem constants
// ---------------------------------------------------------------------------
constexpr int Bb   = 4;
constexpr int Nn   = 4096;
constexpr int DIM  = 512;
constexpr int Hh   = 8;
constexpr int DHd  = 64;
constexpr int Mm   = 256;       // landmarks
constexpr int LMr  = 16;        // tokens per landmark  (N / M)
constexpr int BH   = Bb * Hh;   // 32
constexpr int BN   = Bb * Nn;   // 16384
constexpr int KCONV = 33;

// ---------------------------------------------------------------------------
// Scratch layout (single __device__ buffer, offsets in floats)
// Buffer reuse: outh aliases xn (dead after qkv GEMM); a1z aliases a3
// (dead after a3v GEMM). Total ~460 MB.
// ---------------------------------------------------------------------------
constexpr size_t SZ_XN  = (size_t)BN * DIM;        // 8388608
constexpr size_t SZ_HND = (size_t)BH * Nn * DHd;   // 8388608 (== SZ_XN)
constexpr size_t SZ_L   = (size_t)BH * Mm * DHd;   // 524288
constexpr size_t SZ_A1  = (size_t)BH * Nn * Mm;    // 33554432
constexpr size_t SZ_A2  = (size_t)BH * Mm * Mm;    // 2097152

constexpr size_t OFF_XN   = 0;                     // xn, later reused as outh
constexpr size_t OFF_Q    = OFF_XN  + SZ_XN;
constexpr size_t OFF_K    = OFF_Q   + SZ_HND;
constexpr size_t OFF_V    = OFF_K   + SZ_HND;
constexpr size_t OFF_QL   = OFF_V   + SZ_HND;
constexpr size_t OFF_KL   = OFF_QL  + SZ_L;
constexpr size_t OFF_A1   = OFF_KL  + SZ_L;
constexpr size_t OFF_A3   = OFF_A1  + SZ_A1;       // a3, later reused as a1z
constexpr size_t OFF_A2   = OFF_A3  + SZ_A1;
constexpr size_t OFF_ZA   = OFF_A2  + SZ_A2;
constexpr size_t OFF_ZB   = OFF_ZA  + SZ_A2;
constexpr size_t OFF_P    = OFF_ZB  + SZ_A2;
constexpr size_t OFF_S    = OFF_P   + SZ_A2;
constexpr size_t OFF_U    = OFF_S   + SZ_A2;
constexpr size_t OFF_A3V  = OFF_U   + SZ_A2;
constexpr size_t OFF_SCAL = OFF_A3V + SZ_L;
constexpr size_t TOTAL_F  = OFF_SCAL + 16;

__device__ float g_buf[TOTAL_F];

// ---------------------------------------------------------------------------
// LayerNorm: one block per row of 512, 128 threads, float4 lanes
// ---------------------------------------------------------------------------
__global__ __launch_bounds__(128)
void k_layernorm(const float* __restrict__ x, const float* __restrict__ w,
                 const float* __restrict__ b, float* __restrict__ y)
{
    int row = blockIdx.x, t = threadIdx.x;
    const float4* xp = (const float4*)(x + (size_t)row * DIM);
    float4 xv = xp[t];
    float s  = xv.x + xv.y + xv.z + xv.w;
    float ss = xv.x*xv.x + xv.y*xv.y + xv.z*xv.z + xv.w*xv.w;
    __shared__ float rs[128], rq[128];
    rs[t] = s; rq[t] = ss;
    __syncthreads();
    for (int o = 64; o > 0; o >>= 1) {
        if (t < o) { rs[t] += rs[t+o]; rq[t] += rq[t+o]; }
        __syncthreads();
    }
    float mean = rs[0] * (1.0f / DIM);
    float var  = rq[0] * (1.0f / DIM) - mean * mean;
    float inv  = rsqrtf(var + 1e-5f);
    float4 wv = ((const float4*)w)[t];
    float4 bv = ((const float4*)b)[t];
    float4 o4;
    o4.x = (xv.x - mean) * inv * wv.x + bv.x;
    o4.y = (xv.y - mean) * inv * wv.y + bv.y;
    o4.z = (xv.z - mean) * inv * wv.z + bv.z;
    o4.w = (xv.w - mean) * inv * wv.w + bv.w;
    ((float4*)(y + (size_t)row * DIM))[t] = o4;
}

// ---------------------------------------------------------------------------
// Generic batched 64x64 tile SGEMM (BK=16, 256 thr, 4x4 microtile)
//   C = alpha*(A @ B(^T)) + beta*D + diag*I     (per batch z)
// All dims assumed multiples of 64/16 (true for every call here).
// ---------------------------------------------------------------------------
template<bool TB>
__global__ __launch_bounds__(256)
void gemm64(const float* __restrict__ A, const float* __restrict__ B,
            const float* __restrict__ D, float* __restrict__ C,
            int K, int lda, int ldb, int ldd, int ldc,
            long long sA, long long sB, long long sD, long long sC,
            float alpha, float beta, float diag)
{
    __shared__ float As[16][68];
    __shared__ float Bs[16][68];
    int t  = threadIdx.x;
    int bz = blockIdx.z;
    const float* Ap = A + (size_t)bz * sA;
    const float* Bp = B + (size_t)bz * sB;
    int m0 = blockIdx.y * 64, n0 = blockIdx.x * 64;
    int ty = t >> 4, tx = t & 15;

    float acc[4][4] = {};
    int lmA = t >> 2,  lkA = (t & 3) * 4;   // A: transpose load
    int lkB = t >> 4,  lnB = (t & 15) * 4;  // B NN: direct copy
    int lnT = t >> 2,  lkT = (t & 3) * 4;   // B NT: transpose load

    for (int kt = 0; kt < K; kt += 16) {
        float4 av = *(const float4*)(Ap + (size_t)(m0 + lmA) * lda + kt + lkA);
        As[lkA+0][lmA] = av.x; As[lkA+1][lmA] = av.y;
        As[lkA+2][lmA] = av.z; As[lkA+3][lmA] = av.w;
        if (!TB) {
            float4 bv = *(const float4*)(Bp + (size_t)(kt + lkB) * ldb + n0 + lnB);
            *(float4*)&Bs[lkB][lnB] = bv;
        } else {
            float4 bv = *(const float4*)(Bp + (size_t)(n0 + lnT) * ldb + kt + lkT);
            Bs[lkT+0][lnT] = bv.x; Bs[lkT+1][lnT] = bv.y;
            Bs[lkT+2][lnT] = bv.z; Bs[lkT+3][lnT] = bv.w;
        }
        __syncthreads();
        #pragma unroll
        for (int k = 0; k < 16; k++) {
            float4 a = *(const float4*)&As[k][ty * 4];
            float4 b = *(const float4*)&Bs[k][tx * 4];
            float ar[4] = {a.x, a.y, a.z, a.w};
            float br[4] = {b.x, b.y, b.z, b.w};
            #pragma unroll
            for (int i = 0; i < 4; i++)
                #pragma unroll
                for (int j = 0; j < 4; j++)
                    acc[i][j] = fmaf(ar[i], br[j], acc[i][j]);
        }
        __syncthreads();
    }

    bool hasD = (D != nullptr);
    #pragma unroll
    for (int i = 0; i < 4; i++) {
        int r = m0 + ty * 4 + i;
        #pragma unroll
        for (int j = 0; j < 4; j++) {
            int c = n0 + tx * 4 + j;
            float v = alpha * acc[i][j];
            if (hasD) v += beta * D[(size_t)bz * sD + (size_t)r * ldd + c];
            if (r == c) v += diag;
            C[(size_t)bz * sC + (size_t)r * ldc + c] = v;
        }
    }
}

// ---------------------------------------------------------------------------
// qkv GEMM: xn[16384,512] @ w_qkv[512,1536]; scatter into q/k/v [BH][N][64]
// ---------------------------------------------------------------------------
__global__ __launch_bounds__(256)
void k_gemm_qkv(const float* __restrict__ A, const float* __restrict__ W,
                float* __restrict__ q, float* __restrict__ k, float* __restrict__ v)
{
    __shared__ float As[16][68];
    __shared__ float Bs[16][68];
    int t = threadIdx.x;
    int m0 = blockIdx.y * 64, n0 = blockIdx.x * 64;
    int ty = t >> 4, tx = t & 15;
    float acc[4][4] = {};
    int lmA = t >> 2, lkA = (t & 3) * 4;
    int lkB = t >> 4, lnB = (t & 15) * 4;

    for (int kt = 0; kt < DIM; kt += 16) {
        float4 av = *(const float4*)(A + (size_t)(m0 + lmA) * DIM + kt + lkA);
        As[lkA+0][lmA] = av.x; As[lkA+1][lmA] = av.y;
        As[lkA+2][lmA] = av.z; As[lkA+3][lmA] = av.w;
        float4 bv = *(const float4*)(W + (size_t)(kt + lkB) * 1536 + n0 + lnB);
        *(float4*)&Bs[lkB][lnB] = bv;
        __syncthreads();
        #pragma unroll
        for (int kk = 0; kk < 16; kk++) {
            float4 a = *(const float4*)&As[kk][ty * 4];
            float4 b = *(const float4*)&Bs[kk][tx * 4];
            float ar[4] = {a.x, a.y, a.z, a.w};
            float br[4] = {b.x, b.y, b.z, b.w};
            #pragma unroll
            for (int i = 0; i < 4; i++)
                #pragma unroll
                for (int j = 0; j < 4; j++)
                    acc[i][j] = fmaf(ar[i], br[j], acc[i][j]);
        }
        __syncthreads();
    }

    #pragma unroll
    for (int i = 0; i < 4; i++) {
        int r = m0 + ty * 4 + i;
        int bidx = r >> 12, n = r & (Nn - 1);
        #pragma unroll
        for (int j = 0; j < 4; j++) {
            int c = n0 + tx * 4 + j;
            int which = c >> 9;            // 0=q 1=k 2=v
            int hc = (c >> 6) & 7;
            int d  = c & 63;
            float val = acc[i][j];
            size_t dst = (((size_t)bidx * Hh + hc) * Nn + n) * DHd + d;
            if (which == 0)      q[dst] = val * 0.125f;   // DH^-0.5
            else if (which == 1) k[dst] = val;
            else                 v[dst] = val;
        }
    }
}

// ---------------------------------------------------------------------------
// Landmark means: q_l/k_l[bh,m,d] = mean over 16 tokens
// ---------------------------------------------------------------------------
__global__ __launch_bounds__(256)
void k_landmark(const float* __restrict__ q, const float* __restrict__ k,
                float* __restrict__ ql, float* __restrict__ kl)
{
    int g = blockIdx.x * 256 + threadIdx.x;       // [bh][m][d]
    int d  = g & 63;
    int m  = (g >> 6) & (Mm - 1);
    int bh = g >> 14;
    size_t base = ((size_t)bh * Nn + m * LMr) * DHd + d;
    float sq = 0.f, sk = 0.f;
    #pragma unroll
    for (int j = 0; j < LMr; j++) {
        sq += q[base + (size_t)j * DHd];
        sk += k[base + (size_t)j * DHd];
    }
    ql[g] = sq * (1.0f / LMr);
    kl[g] = sk * (1.0f / LMr);
}

// ---------------------------------------------------------------------------
// Row softmax (in-place).  L in {256, 4096}; 256 threads/row
// ---------------------------------------------------------------------------
__global__ __launch_bounds__(256)
void k_softmax(float* __restrict__ X, int L)
{
    int row = blockIdx.x, t = threadIdx.x;
    float* p = X + (size_t)row * L;
    int per = L >> 8;
    float vals[16];
    float mx = -1e30f;
    for (int i = 0; i < per; i++) { vals[i] = p[t + (i << 8)]; mx = fmaxf(mx, vals[i]); }
    __shared__ float red[256];
    red[t] = mx; __syncthreads();
    for (int o = 128; o > 0; o >>= 1) { if (t < o) red[t] = fmaxf(red[t], red[t+o]); __syncthreads(); }
    mx = red[0]; __syncthreads();
    float sum = 0.f;
    for (int i = 0; i < per; i++) { vals[i] = __expf(vals[i] - mx); sum += vals[i]; }
    red[t] = sum; __syncthreads();
    for (int o = 128; o > 0; o >>= 1) { if (t < o) red[t] += red[t+o]; __syncthreads(); }
    float inv = 1.0f / red[0];
    for (int i = 0; i < per; i++) p[t + (i << 8)] = vals[i] * inv;
}

// ---------------------------------------------------------------------------
// pinv init: global max of row-sums / col-sums of a2 (positive floats)
// ---------------------------------------------------------------------------
__global__ void k_reset_scal(float* scal) { if (threadIdx.x < 2) scal[threadIdx.x] = 0.f; }

__global__ __launch_bounds__(256)
void k_rowmax(const float* __restrict__ a2, float* scal)   // 8192 blocks (bh*M rows)
{
    int row = blockIdx.x, t = threadIdx.x;
    float v = a2[(size_t)row * Mm + t];
    __shared__ float red[256];
    red[t] = v; __syncthreads();
    for (int o = 128; o > 0; o >>= 1) { if (t < o) red[t] += red[t+o]; __syncthreads(); }
    if (t == 0) atomicMax((unsigned*)&scal[0], __float_as_uint(red[0]));
}

__global__ __launch_bounds__(256)
void k_colmax(const float* __restrict__ a2, float* scal)   // 32 blocks (bh)
{
    int bh = blockIdx.x, j = threadIdx.x;
    const float* p = a2 + ((size_t)bh << 16) + j;
    float s = 0.f;
    for (int i = 0; i < Mm; i++) s += p[(size_t)i * Mm];
    __shared__ float red[256];
    red[j] = s; __syncthreads();
    for (int o = 128; o > 0; o >>= 1) { if (j < o) red[j] = fmaxf(red[j], red[j+o]); __syncthreads(); }
    if (j == 0) atomicMax((unsigned*)&scal[1], __float_as_uint(red[0]));
}

__global__ __launch_bounds__(256)
void k_zinit(const float* __restrict__ a2, float* __restrict__ z, const float* scal)
{
    int g = blockIdx.x * 256 + threadIdx.x;   // [bh][i][j]
    float inv = 1.0f / (scal[0] * scal[1]);
    int j = g & 255, i = (g >> 8) & 255, bh = g >> 16;
    z[g] = a2[((size_t)bh << 16) + (size_t)j * Mm + i] * inv;   // transpose
}

// ---------------------------------------------------------------------------
// Depthwise residual conv over sequence: outh += conv33(v)
// ---------------------------------------------------------------------------
__global__ __launch_bounds__(256)
void k_conv(const float* __restrict__ v, const float* __restrict__ rw,
            float* __restrict__ outh)
{
    int bh = blockIdx.y;
    int n0 = blockIdx.x * 64;
    __shared__ float vs[96][64];
    __shared__ float ws[KCONV];
    int t = threadIdx.x;
    const float* vp = v + (size_t)bh * Nn * DHd;
    for (int idx = t; idx < 96 * 64; idx += 256) {
        int r = idx >> 6, d = idx & 63;
        int n = n0 - 16 + r;
        vs[r][d] = (n >= 0 && n < Nn) ? vp[(size_t)n * DHd + d] : 0.0f;
    }
    if (t < KCONV) ws[t] = rw[(bh & 7) * KCONV + t];
    __syncthreads();
    int d = t & 63, r0 = t >> 6;
    for (int nn = r0; nn < 64; nn += 4) {
        float acc = 0.f;
        #pragma unroll
        for (int tt = 0; tt < KCONV; tt++)
            acc = fmaf(ws[tt], vs[nn + tt][d], acc);
        outh[((size_t)bh * Nn + n0 + nn) * DHd + d] += acc;
    }
}

// ---------------------------------------------------------------------------
// Final GEMM: gather heads, @ w_out [512,512], + b_out + x residual
// ---------------------------------------------------------------------------
__global__ __launch_bounds__(256)
void k_gemm_final(const float* __restrict__ outh, const float* __restrict__ W,
                  const float* __restrict__ bout, const float* __restrict__ x,
                  float* __restrict__ out)
{
    __shared__ float As[16][68];
    __shared__ float Bs[16][68];
    int t = threadIdx.x;
    int m0 = blockIdx.y * 64, n0 = blockIdx.x * 64;
    int ty = t >> 4, tx = t & 15;
    float acc[4][4] = {};
    int lmA = t >> 2, lkA = (t & 3) * 4;
    int lkB = t >> 4, lnB = (t & 15) * 4;

    for (int kt = 0; kt < DIM; kt += 16) {
        int r = m0 + lmA;
        int bidx = r >> 12, n = r & (Nn - 1);
        int cc = kt + lkA;
        int h = cc >> 6, d = cc & 63;
        float4 av = *(const float4*)(outh + (((size_t)bidx * Hh + h) * Nn + n) * DHd + d);
        As[lkA+0][lmA] = av.x; As[lkA+1][lmA] = av.y;
        As[lkA+2][lmA] = av.z; As[lkA+3][lmA] = av.w;
        float4 bv = *(const float4*)(W + (size_t)(kt + lkB) * DIM + n0 + lnB);
        *(float4*)&Bs[lkB][lnB] = bv;
        __syncthreads();
        #pragma unroll
        for (int kk = 0; kk < 16; kk++) {
            float4 a = *(const float4*)&As[kk][ty * 4];
            float4 b = *(const float4*)&Bs[kk][tx * 4];
            float ar[4] = {a.x, a.y, a.z, a.w};
            float br[4] = {b.x, b.y, b.z, b.w};
            #pragma unroll
            for (int i = 0; i < 4; i++)
                #pragma unroll
                for (int j = 0; j < 4; j++)
                    acc[i][j] = fmaf(ar[i], br[j], acc[i][j]);
        }
        __syncthreads();
    }

    #pragma unroll
    for (int i = 0; i < 4; i++) {
        int r = m0 + ty * 4 + i;
        #pragma unroll
        for (int j = 0; j < 4; j++) {
            int c = n0 + tx * 4 + j;
            out[(size_t)r * DIM + c] = acc[i][j] + bout[c] + x[(size_t)r * DIM + c];
        }
    }
}

// ---------------------------------------------------------------------------
// Host-side launch helpers
// ---------------------------------------------------------------------------
static inline void gemm_nn(const float* A, const float* B, const float* D, float* C,
                           int M, int N, int K, int lda, int ldb, int ldd, int ldc,
                           long long sA, long long sB, long long sD, long long sC,
                           int batch, float alpha, float beta, float diag)
{
    gemm64<false><<<dim3(N / 64, M / 64, batch), 256>>>(
        A, B, D, C, K, lda, ldb, ldd, ldc, sA, sB, sD, sC, alpha, beta, diag);
}
static inline void gemm_nt(const float* A, const float* B, const float* D, float* C,
                           int M, int N, int K, int lda, int ldb, int ldd, int ldc,
                           long long sA, long long sB, long long sD, long long sC,
                           int batch, float alpha, float beta, float diag)
{
    gemm64<true><<<dim3(N / 64, M / 64, batch), 256>>>(
        A, B, D, C, K, lda, ldb, ldd, ldc, sA, sB, sD, sC, alpha, beta, diag);
}

extern "C" void kernel_launch(void* const* d_in, const int* in_sizes, int n_in,
                              void* d_out, int out_size)
{
    const float* x      = (const float*)d_in[0];
    const float* norm_w = (const float*)d_in[1];
    const float* norm_b = (const float*)d_in[2];
    const float* w_qkv  = (const float*)d_in[3];
    const float* w_out  = (const float*)d_in[4];
    const float* b_out  = (const float*)d_in[5];
    const float* res_w  = (const float*)d_in[6];
    float* out = (float*)d_out;

    float* buf = nullptr;
    cudaGetSymbolAddress((void**)&buf, g_buf);

    float* xn   = buf + OFF_XN;
    float* q    = buf + OFF_Q;
    float* k    = buf + OFF_K;
    float* v    = buf + OFF_V;
    float* ql   = buf + OFF_QL;
    float* kl   = buf + OFF_KL;
    float* a1   = buf + OFF_A1;
    float* a3   = buf + OFF_A3;
    float* a2   = buf + OFF_A2;
    float* zA   = buf + OFF_ZA;
    float* zB   = buf + OFF_ZB;
    float* P    = buf + OFF_P;
    float* S    = buf + OFF_S;
    float* U    = buf + OFF_U;
    float* a3v  = buf + OFF_A3V;
    float* scal = buf + OFF_SCAL;
    float* a1z  = a3;   // reuse: a3 dead after a3v GEMM (stream-ordered before a1z GEMM)
    float* outh = xn;   // reuse: xn dead after qkv GEMM (same size)

    // 1. LayerNorm
    k_layernorm<<<BN, 128>>>(x, norm_w, norm_b, xn);

    // 2. qkv projection (+ q scale, head-major scatter)
    k_gemm_qkv<<<dim3(1536 / 64, BN / 64, 1), 256>>>(xn, w_qkv, q, k, v);

    // 3. landmarks
    k_landmark<<<(int)(SZ_L / 256), 256>>>(q, k, ql, kl);

    // 4. similarity GEMMs (NT, K=64)
    const long long sQ = (long long)Nn * DHd, sL = (long long)Mm * DHd;
    gemm_nt(q,  kl, nullptr, a1, Nn, Mm, DHd, DHd, DHd, 0, Mm,
            sQ, sL, 0, (long long)Nn * Mm, BH, 1.f, 0.f, 0.f);
    gemm_nt(ql, kl, nullptr, a2, Mm, Mm, DHd, DHd, DHd, 0, Mm,
            sL, sL, 0, (long long)Mm * Mm, BH, 1.f, 0.f, 0.f);
    gemm_nt(ql, k,  nullptr, a3, Mm, Nn, DHd, DHd, DHd, 0, Nn,
            sL, sQ, 0, (long long)Mm * Nn, BH, 1.f, 0.f, 0.f);

    // 5. softmaxes (in place)
    k_softmax<<<BH * Nn, 256>>>(a1, Mm);
    k_softmax<<<BH * Mm, 256>>>(a2, Mm);
    k_softmax<<<BH * Mm, 256>>>(a3, Nn);

    // 6. pinv init: z = a2^T / (max(rowsum) * max(colsum))   (global maxes)
    k_reset_scal<<<1, 32>>>(scal);
    k_rowmax<<<BH * Mm, 256>>>(a2, scal);
    k_colmax<<<BH, 256>>>(a2, scal);
    k_zinit<<<(int)(SZ_A2 / 256), 256>>>(a2, zA, scal);

    // 7. Newton-Schulz iterations (6), batched 256^3 GEMMs
    //    P = a2 @ z;  S = P@P - 7P + 15I;  U = 13I - P@S;  z' = 0.25 z@U
    const long long s2 = (long long)Mm * Mm;
    float* zc = zA; float* zn = zB;
    for (int it = 0; it < 6; it++) {
        gemm_nn(a2, zc, nullptr, P, Mm, Mm, Mm, Mm, Mm, 0, Mm,
                s2, s2, 0, s2, BH, 1.f, 0.f, 0.f);
        gemm_nn(P, P, P, S, Mm, Mm, Mm, Mm, Mm, Mm, Mm,
                s2, s2, s2, s2, BH, 1.f, -7.f, 15.f);
        gemm_nn(P, S, nullptr, U, Mm, Mm, Mm, Mm, Mm, 0, Mm,
                s2, s2, 0, s2, BH, -1.f, 0.f, 13.f);
        gemm_nn(zc, U, nullptr, zn, Mm, Mm, Mm, Mm, Mm, 0, Mm,
                s2, s2, 0, s2, BH, 0.25f, 0.f, 0.f);
        float* tmp = zc; zc = zn; zn = tmp;
    }
    // after even number of swaps, zc == zA holds the result

    // 8. a3v = a3 @ v          [M x DH]   (a3 dead after this)
    gemm_nn(a3, v, nullptr, a3v, Mm, DHd, Nn, Nn, DHd, 0, DHd,
            (long long)Mm * Nn, sQ, 0, (long long)Mm * DHd, BH, 1.f, 0.f, 0.f);

    // 9. a1z = a1 @ z          [N x M]    (writes into a3's buffer)
    gemm_nn(a1, zc, nullptr, a1z, Nn, Mm, Mm, Mm, Mm, 0, Mm,
            (long long)Nn * Mm, s2, 0, (long long)Nn * Mm, BH, 1.f, 0.f, 0.f);

    // 10. outh = a1z @ a3v     [N x DH]   (writes into xn's buffer)
    gemm_nn(a1z, a3v, nullptr, outh, Nn, DHd, Mm, Mm, DHd, 0, DHd,
            (long long)Nn * Mm, (long long)Mm * DHd, 0, sQ, BH, 1.f, 0.f, 0.f);

    // 11. residual depthwise conv over sequence
    k_conv<<<dim3(Nn / 64, BH), 256>>>(v, res_w, outh);

    // 12. final: out = x + (heads-gathered outh) @ w_out + b_out
    k_gemm_final<<<dim3(DIM / 64, BN / 64, 1), 256>>>(outh, w_out, b_out, x, out);
}

// round 5
// speedup vs baseline: 1.9524x; 1.9524x over previous
#include <cuda_runtime.h>
#include <cstdint>
#include <cstddef>

// ---------------------------------------------------------------------------
// Problem constants
// ---------------------------------------------------------------------------
constexpr int Bb   = 4;
constexpr int Nn   = 4096;
constexpr int DIM  = 512;
constexpr int Hh   = 8;
constexpr int DHd  = 64;
constexpr int Mm   = 256;       // landmarks
constexpr int LMr  = 16;        // tokens per landmark  (N / M)
constexpr int BH   = Bb * Hh;   // 32
constexpr int BN   = Bb * Nn;   // 16384
constexpr int KCONV = 33;

// ---------------------------------------------------------------------------
// Scratch layout (single __device__ buffer, offsets in floats). ~460 MB.
// outg (gathered out-heads) aliases xn; a1z aliases a3.
// ---------------------------------------------------------------------------
constexpr size_t SZ_XN  = (size_t)BN * DIM;        // 8388608
constexpr size_t SZ_HND = (size_t)BH * Nn * DHd;   // 8388608
constexpr size_t SZ_L   = (size_t)BH * Mm * DHd;   // 524288
constexpr size_t SZ_A1  = (size_t)BH * Nn * Mm;    // 33554432
constexpr size_t SZ_A2  = (size_t)BH * Mm * Mm;    // 2097152

constexpr size_t OFF_XN   = 0;                     // xn, later reused as outg
constexpr size_t OFF_Q    = OFF_XN  + SZ_XN;
constexpr size_t OFF_K    = OFF_Q   + SZ_HND;
constexpr size_t OFF_V    = OFF_K   + SZ_HND;
constexpr size_t OFF_QL   = OFF_V   + SZ_HND;
constexpr size_t OFF_KL   = OFF_QL  + SZ_L;
constexpr size_t OFF_A1   = OFF_KL  + SZ_L;
constexpr size_t OFF_A3   = OFF_A1  + SZ_A1;       // a3, later reused as a1z
constexpr size_t OFF_A2   = OFF_A3  + SZ_A1;
constexpr size_t OFF_ZA   = OFF_A2  + SZ_A2;
constexpr size_t OFF_ZB   = OFF_ZA  + SZ_A2;
constexpr size_t OFF_P    = OFF_ZB  + SZ_A2;
constexpr size_t OFF_S    = OFF_P   + SZ_A2;
constexpr size_t OFF_U    = OFF_S   + SZ_A2;
constexpr size_t OFF_A3V  = OFF_U   + SZ_A2;
constexpr size_t OFF_SCAL = OFF_A3V + SZ_L;
constexpr size_t TOTAL_F  = OFF_SCAL + 16;

__device__ float g_buf[TOTAL_F];

// ---------------------------------------------------------------------------
// tf32 helpers
// ---------------------------------------------------------------------------
__device__ __forceinline__ float to_tf32(float f) {
    uint32_t u;
    asm("cvt.rna.tf32.f32 %0, %1;" : "=r"(u) : "f"(f));
    return __uint_as_float(u);
}

__device__ __forceinline__ void mma_tf32(float* c, const uint4& a, const uint2& b) {
    asm volatile(
        "mma.sync.aligned.m16n8k8.row.col.f32.tf32.tf32.f32 "
        "{%0,%1,%2,%3}, {%4,%5,%6,%7}, {%8,%9}, {%0,%1,%2,%3};\n"
        : "+f"(c[0]), "+f"(c[1]), "+f"(c[2]), "+f"(c[3])
        : "r"(a.x), "r"(a.y), "r"(a.z), "r"(a.w), "r"(b.x), "r"(b.y));
}

// ---------------------------------------------------------------------------
// Tensor-core tf32 GEMM.
//   C = alpha*(A @ B(^T)) + beta*D + diag*I     (epi 0, per batch z)
//   epi 1: qkv scatter (C=q, e3=k, e4=v), q scaled 0.125
//   epi 2: C = acc + e1[col] + e2[row*ldc+col]     (bias + residual)
//   epi 3: head-scatter: C[(b*Nn+r)*DIM + h*64 + c], bh = blockIdx.z
// BM x BNt block tile, BK=16, 256 threads (8 warps), warp tile WM x WN.
// SMEM fragment-major layout with XOR swizzles; double buffered.
// ---------------------------------------------------------------------------
template<int BM, int BNt, int WM, int WN, bool TB>
__global__ __launch_bounds__(256)
void tgemm(const float* __restrict__ A, const float* __restrict__ B,
           const float* __restrict__ D, float* __restrict__ C,
           int K, int lda, int ldb, int ldd, int ldc,
           long long sA, long long sB, long long sD, long long sC,
           float alpha, float beta, float diag,
           int epi, const float* __restrict__ e1, const float* __restrict__ e2,
           float* __restrict__ e3, float* __restrict__ e4)
{
    constexpr int MT  = WM / 16;          // m16 tiles per warp
    constexpr int NTn = WN / 8;           // n8 tiles per warp
    constexpr int WCOLS = BNt / WN;
    constexpr int ATILES = BM / 16;       // m tiles per block
    constexpr int BTILES = BNt / 8;       // n tiles per block
    constexpr int ASZ = 2 * ATILES * 128; // floats per buffer (2 k-tiles)
    constexpr int BSZ = 2 * BTILES * 64;
    constexpr int AQ = BM / 64;           // float4 loads per thread (A chunk)
    constexpr int BQ = BNt / 64;
    static_assert((BM / WM) * WCOLS == 8, "8 warps");

    __shared__ float As[2][ASZ];
    __shared__ float Bs[2][BSZ];

    int tid = threadIdx.x, lane = tid & 31, warp = tid >> 5;
    int wm = warp / WCOLS, wn = warp % WCOLS;
    int bz = blockIdx.z;
    int m0 = blockIdx.y * BM, n0 = blockIdx.x * BNt;
    const float* Ap = A + (size_t)bz * sA;
    const float* Bp = B + (size_t)bz * sB;

    float acc[MT][NTn][4];
    #pragma unroll
    for (int i = 0; i < MT; i++)
        #pragma unroll
        for (int j = 0; j < NTn; j++)
            #pragma unroll
            for (int r = 0; r < 4; r++) acc[i][j][r] = 0.f;

    // fragment-major store helpers (with bank-conflict XOR swizzles)
    auto stA = [&](int buf, int m, int kk, float val) {
        int mtile = m >> 4, mloc = m & 15;
        int ktile = kk >> 3, kloc = kk & 7;
        int la = ((mloc & 7) << 2) | (kloc & 3);
        la ^= (la >> 3) & 3;
        int reg = (mloc >> 3) | ((kloc >> 2) << 1);
        As[buf][(ktile * ATILES + mtile) * 128 + la * 4 + reg] = val;
    };
    auto stB = [&](int buf, int kk, int n, float val) {
        int ntile = n >> 3, nloc = n & 7;
        int ktile = kk >> 3, kloc = kk & 7;
        int lb = (nloc << 2) | (kloc & 3);
        lb ^= ((ntile & 3) << 2) | ((ntile >> 2) & 3);
        int reg = kloc >> 2;
        Bs[buf][(ktile * BTILES + ntile) * 64 + lb * 2 + reg] = val;
    };

    auto ldgA = [&](int kt, float4* pr) {
        #pragma unroll
        for (int i = 0; i < AQ; i++) {
            int q = i * 256 + tid;
            int m = q >> 2, kq = (q & 3) << 2;
            pr[i] = *(const float4*)(Ap + (size_t)(m0 + m) * lda + kt + kq);
        }
    };
    auto cmtA = [&](int buf, const float4* pr) {
        #pragma unroll
        for (int i = 0; i < AQ; i++) {
            int q = i * 256 + tid;
            int m = q >> 2, kq = (q & 3) << 2;
            stA(buf, m, kq + 0, to_tf32(pr[i].x));
            stA(buf, m, kq + 1, to_tf32(pr[i].y));
            stA(buf, m, kq + 2, to_tf32(pr[i].z));
            stA(buf, m, kq + 3, to_tf32(pr[i].w));
        }
    };
    auto ldgB = [&](int kt, float4* pr) {
        #pragma unroll
        for (int i = 0; i < BQ; i++) {
            int q = i * 256 + tid;
            if (!TB) {
                int kk = q / (BNt / 4), n = (q % (BNt / 4)) * 4;
                pr[i] = *(const float4*)(Bp + (size_t)(kt + kk) * ldb + n0 + n);
            } else {
                int n = q >> 2, kq = (q & 3) << 2;
                pr[i] = *(const float4*)(Bp + (size_t)(n0 + n) * ldb + kt + kq);
            }
        }
    };
    auto cmtB = [&](int buf, const float4* pr) {
        #pragma unroll
        for (int i = 0; i < BQ; i++) {
            int q = i * 256 + tid;
            if (!TB) {
                int kk = q / (BNt / 4), n = (q % (BNt / 4)) * 4;
                stB(buf, kk, n + 0, to_tf32(pr[i].x));
                stB(buf, kk, n + 1, to_tf32(pr[i].y));
                stB(buf, kk, n + 2, to_tf32(pr[i].z));
                stB(buf, kk, n + 3, to_tf32(pr[i].w));
            } else {
                int n = q >> 2, kq = (q & 3) << 2;
                stB(buf, kq + 0, n, to_tf32(pr[i].x));
                stB(buf, kq + 1, n, to_tf32(pr[i].y));
                stB(buf, kq + 2, n, to_tf32(pr[i].z));
                stB(buf, kq + 3, n, to_tf32(pr[i].w));
            }
        }
    };

    int nch = K >> 4;
    float4 pa[AQ], pb[BQ];
    ldgA(0, pa); ldgB(0, pb);
    cmtA(0, pa); cmtB(0, pb);
    __syncthreads();

    int buf = 0;
    int laAddr = (lane ^ ((lane >> 3) & 3)) * 4;
    for (int c = 0; c < nch; c++) {
        bool more = (c + 1 < nch);
        if (more) { ldgA((c + 1) << 4, pa); ldgB((c + 1) << 4, pb); }
        #pragma unroll
        for (int ks = 0; ks < 2; ks++) {
            uint4 af[MT]; uint2 bf[NTn];
            #pragma unroll
            for (int mt = 0; mt < MT; mt++)
                af[mt] = *(const uint4*)&As[buf][(ks * ATILES + wm * MT + mt) * 128 + laAddr];
            #pragma unroll
            for (int nt = 0; nt < NTn; nt++) {
                int ntile = wn * NTn + nt;
                int swz = ((ntile & 3) << 2) | ((ntile >> 2) & 3);
                bf[nt] = *(const uint2*)&Bs[buf][(ks * BTILES + ntile) * 64 + (lane ^ swz) * 2];
            }
            #pragma unroll
            for (int mt = 0; mt < MT; mt++)
                #pragma unroll
                for (int nt = 0; nt < NTn; nt++)
                    mma_tf32(acc[mt][nt], af[mt], bf[nt]);
        }
        if (more) { cmtA(buf ^ 1, pa); cmtB(buf ^ 1, pb); __syncthreads(); buf ^= 1; }
    }

    // epilogue
    int rw = m0 + wm * WM;
    int cw = n0 + wn * WN;
    bool hasD = (D != nullptr);
    #pragma unroll
    for (int mt = 0; mt < MT; mt++) {
        #pragma unroll
        for (int nt = 0; nt < NTn; nt++) {
            int rbase = rw + mt * 16 + (lane >> 2);
            int cc = cw + nt * 8 + (lane & 3) * 2;
            const float* a4 = acc[mt][nt];
            #pragma unroll
            for (int half = 0; half < 2; half++) {
                int rr = rbase + half * 8;
                float v0 = a4[half * 2 + 0], v1 = a4[half * 2 + 1];
                if (epi == 0) {
                    v0 *= alpha; v1 *= alpha;
                    if (hasD) {
                        size_t od = (size_t)bz * sD + (size_t)rr * ldd + cc;
                        v0 += beta * D[od];
                        v1 += beta * D[od + 1];
                    }
                    if (rr == cc)     v0 += diag;
                    if (rr == cc + 1) v1 += diag;
                    size_t oc = (size_t)bz * sC + (size_t)rr * ldc + cc;
                    C[oc] = v0; C[oc + 1] = v1;
                } else if (epi == 1) {
                    int bidx = rr >> 12, n = rr & (Nn - 1);
                    #pragma unroll
                    for (int u = 0; u < 2; u++) {
                        int c1 = cc + u;
                        float val = u ? v1 : v0;
                        int which = c1 >> 9, hc = (c1 >> 6) & 7, d = c1 & 63;
                        size_t dst = (((size_t)bidx * Hh + hc) * Nn + n) * DHd + d;
                        if (which == 0)      C[dst]  = val * 0.125f;
                        else if (which == 1) e3[dst] = val;
                        else                 e4[dst] = val;
                    }
                } else if (epi == 2) {
                    size_t o = (size_t)rr * ldc;
                    C[o + cc]     = v0 + e1[cc]     + e2[o + cc];
                    C[o + cc + 1] = v1 + e1[cc + 1] + e2[o + cc + 1];
                } else {   // epi 3: head scatter (bz = bh)
                    int b = bz >> 3, h = bz & 7;
                    size_t o = ((size_t)(b * Nn + rr)) * DIM + h * DHd;
                    C[o + cc] = v0; C[o + cc + 1] = v1;
                }
            }
        }
    }
}

// ---------------------------------------------------------------------------
// LayerNorm
// ---------------------------------------------------------------------------
__global__ __launch_bounds__(128)
void k_layernorm(const float* __restrict__ x, const float* __restrict__ w,
                 const float* __restrict__ b, float* __restrict__ y)
{
    int row = blockIdx.x, t = threadIdx.x;
    const float4* xp = (const float4*)(x + (size_t)row * DIM);
    float4 xv = xp[t];
    float s  = xv.x + xv.y + xv.z + xv.w;
    float ss = xv.x*xv.x + xv.y*xv.y + xv.z*xv.z + xv.w*xv.w;
    __shared__ float rs[128], rq[128];
    rs[t] = s; rq[t] = ss;
    __syncthreads();
    for (int o = 64; o > 0; o >>= 1) {
        if (t < o) { rs[t] += rs[t+o]; rq[t] += rq[t+o]; }
        __syncthreads();
    }
    float mean = rs[0] * (1.0f / DIM);
    float var  = rq[0] * (1.0f / DIM) - mean * mean;
    float inv  = rsqrtf(var + 1e-5f);
    float4 wv = ((const float4*)w)[t];
    float4 bv = ((const float4*)b)[t];
    float4 o4;
    o4.x = (xv.x - mean) * inv * wv.x + bv.x;
    o4.y = (xv.y - mean) * inv * wv.y + bv.y;
    o4.z = (xv.z - mean) * inv * wv.z + bv.z;
    o4.w = (xv.w - mean) * inv * wv.w + bv.w;
    ((float4*)(y + (size_t)row * DIM))[t] = o4;
}

// ---------------------------------------------------------------------------
// Landmark means
// ---------------------------------------------------------------------------
__global__ __launch_bounds__(256)
void k_landmark(const float* __restrict__ q, const float* __restrict__ k,
                float* __restrict__ ql, float* __restrict__ kl)
{
    int g = blockIdx.x * 256 + threadIdx.x;
    int d  = g & 63;
    int m  = (g >> 6) & (Mm - 1);
    int bh = g >> 14;
    size_t base = ((size_t)bh * Nn + m * LMr) * DHd + d;
    float sq = 0.f, sk = 0.f;
    #pragma unroll
    for (int j = 0; j < LMr; j++) {
        sq += q[base + (size_t)j * DHd];
        sk += k[base + (size_t)j * DHd];
    }
    ql[g] = sq * (1.0f / LMr);
    kl[g] = sk * (1.0f / LMr);
}

// ---------------------------------------------------------------------------
// Row softmax (in-place), L in {256, 4096}
// ---------------------------------------------------------------------------
__global__ __launch_bounds__(256)
void k_softmax(float* __restrict__ X, int L)
{
    int row = blockIdx.x, t = threadIdx.x;
    float* p = X + (size_t)row * L;
    int per = L >> 8;
    float vals[16];
    float mx = -1e30f;
    for (int i = 0; i < per; i++) { vals[i] = p[t + (i << 8)]; mx = fmaxf(mx, vals[i]); }
    __shared__ float red[256];
    red[t] = mx; __syncthreads();
    for (int o = 128; o > 0; o >>= 1) { if (t < o) red[t] = fmaxf(red[t], red[t+o]); __syncthreads(); }
    mx = red[0]; __syncthreads();
    float sum = 0.f;
    for (int i = 0; i < per; i++) { vals[i] = __expf(vals[i] - mx); sum += vals[i]; }
    red[t] = sum; __syncthreads();
    for (int o = 128; o > 0; o >>= 1) { if (t < o) red[t] += red[t+o]; __syncthreads(); }
    float inv = 1.0f / red[0];
    for (int i = 0; i < per; i++) p[t + (i << 8)] = vals[i] * inv;
}

// ---------------------------------------------------------------------------
// pinv init scalars
// ---------------------------------------------------------------------------
__global__ void k_reset_scal(float* scal) { if (threadIdx.x < 2) scal[threadIdx.x] = 0.f; }

__global__ __launch_bounds__(256)
void k_rowmax(const float* __restrict__ a2, float* scal)
{
    int row = blockIdx.x, t = threadIdx.x;
    float v = a2[(size_t)row * Mm + t];
    __shared__ float red[256];
    red[t] = v; __syncthreads();
    for (int o = 128; o > 0; o >>= 1) { if (t < o) red[t] += red[t+o]; __syncthreads(); }
    if (t == 0) atomicMax((unsigned*)&scal[0], __float_as_uint(red[0]));
}

__global__ __launch_bounds__(256)
void k_colmax(const float* __restrict__ a2, float* scal)
{
    int bh = blockIdx.x, j = threadIdx.x;
    const float* p = a2 + ((size_t)bh << 16) + j;
    float s = 0.f;
    for (int i = 0; i < Mm; i++) s += p[(size_t)i * Mm];
    __shared__ float red[256];
    red[j] = s; __syncthreads();
    for (int o = 128; o > 0; o >>= 1) { if (j < o) red[j] = fmaxf(red[j], red[j+o]); __syncthreads(); }
    if (j == 0) atomicMax((unsigned*)&scal[1], __float_as_uint(red[0]));
}

__global__ __launch_bounds__(256)
void k_zinit(const float* __restrict__ a2, float* __restrict__ z, const float* scal)
{
    int g = blockIdx.x * 256 + threadIdx.x;
    float inv = 1.0f / (scal[0] * scal[1]);
    int j = g & 255, i = (g >> 8) & 255, bh = g >> 16;
    z[g] = a2[((size_t)bh << 16) + (size_t)j * Mm + i] * inv;
}

// ---------------------------------------------------------------------------
// Depthwise residual conv over sequence: outg(gathered) += conv33(v)
// ---------------------------------------------------------------------------
__global__ __launch_bounds__(256)
void k_conv(const float* __restrict__ v, const float* __restrict__ rw,
            float* __restrict__ outg)
{
    int bh = blockIdx.y;
    int b = bh >> 3, h = bh & 7;
    int n0 = blockIdx.x * 64;
    __shared__ float vs[96][64];
    __shared__ float ws[KCONV];
    int t = threadIdx.x;
    const float* vp = v + (size_t)bh * Nn * DHd;
    for (int idx = t; idx < 96 * 64; idx += 256) {
        int r = idx >> 6, d = idx & 63;
        int n = n0 - 16 + r;
        vs[r][d] = (n >= 0 && n < Nn) ? vp[(size_t)n * DHd + d] : 0.0f;
    }
    if (t < KCONV) ws[t] = rw[h * KCONV + t];
    __syncthreads();
    int d = t & 63, r0 = t >> 6;
    for (int nn = r0; nn < 64; nn += 4) {
        float acc = 0.f;
        #pragma unroll
        for (int tt = 0; tt < KCONV; tt++)
            acc = fmaf(ws[tt], vs[nn + tt][d], acc);
        outg[((size_t)(b * Nn + n0 + nn)) * DIM + h * DHd + d] += acc;
    }
}

// ---------------------------------------------------------------------------
// Host-side launch helpers (3 tgemm instantiations total)
// ---------------------------------------------------------------------------
static inline void tg_nn(const float* A, const float* B, const float* D, float* C,
                         int M, int N, int K, int lda, int ldb, int ldd, int ldc,
                         long long sA, long long sB, long long sD, long long sC,
                         int batch, float alpha, float beta, float diag,
                         int epi = 0, const float* e1 = nullptr, const float* e2 = nullptr,
                         float* e3 = nullptr, float* e4 = nullptr)
{
    tgemm<128,128,64,32,false><<<dim3(N/128, M/128, batch), 256>>>(
        A, B, D, C, K, lda, ldb, ldd, ldc, sA, sB, sD, sC,
        alpha, beta, diag, epi, e1, e2, e3, e4);
}
static inline void tg_nt(const float* A, const float* B, const float* D, float* C,
                         int M, int N, int K, int lda, int ldb, int ldd, int ldc,
                         long long sA, long long sB, long long sD, long long sC,
                         int batch, float alpha, float beta, float diag)
{
    tgemm<128,128,64,32,true><<<dim3(N/128, M/128, batch), 256>>>(
        A, B, D, C, K, lda, ldb, ldd, ldc, sA, sB, sD, sC,
        alpha, beta, diag, 0, nullptr, nullptr, nullptr, nullptr);
}
// 128x64 tile variant (N=64 GEMMs: a3v and outg)
static inline void tg_nn64(const float* A, const float* B, float* C,
                           int M, int K, int lda, int ldb, int ldc,
                           long long sA, long long sB, long long sC,
                           int batch, int epi)
{
    tgemm<128,64,32,32,false><<<dim3(1, M/128, batch), 256>>>(
        A, B, nullptr, C, K, lda, ldb, 0, ldc, sA, sB, 0, sC,
        1.f, 0.f, 0.f, epi, nullptr, nullptr, nullptr, nullptr);
}

extern "C" void kernel_launch(void* const* d_in, const int* in_sizes, int n_in,
                              void* d_out, int out_size)
{
    const float* x      = (const float*)d_in[0];
    const float* norm_w = (const float*)d_in[1];
    const float* norm_b = (const float*)d_in[2];
    const float* w_qkv  = (const float*)d_in[3];
    const float* w_out  = (const float*)d_in[4];
    const float* b_out  = (const float*)d_in[5];
    const float* res_w  = (const float*)d_in[6];
    float* out = (float*)d_out;

    float* buf = nullptr;
    cudaGetSymbolAddress((void**)&buf, g_buf);

    float* xn   = buf + OFF_XN;
    float* q    = buf + OFF_Q;
    float* k    = buf + OFF_K;
    float* v    = buf + OFF_V;
    float* ql   = buf + OFF_QL;
    float* kl   = buf + OFF_KL;
    float* a1   = buf + OFF_A1;
    float* a3   = buf + OFF_A3;
    float* a2   = buf + OFF_A2;
    float* zA   = buf + OFF_ZA;
    float* zB   = buf + OFF_ZB;
    float* P    = buf + OFF_P;
    float* S    = buf + OFF_S;
    float* U    = buf + OFF_U;
    float* a3v  = buf + OFF_A3V;
    float* scal = buf + OFF_SCAL;
    float* a1z  = a3;   // reuse (a3 dead after a3v GEMM)
    float* outg = xn;   // reuse (xn dead after qkv GEMM); gathered [BN][DIM]

    const long long sQ = (long long)Nn * DHd, sL = (long long)Mm * DHd;
    const long long s2 = (long long)Mm * Mm;
    const long long sA1 = (long long)Nn * Mm;

    // 1. LayerNorm
    k_layernorm<<<BN, 128>>>(x, norm_w, norm_b, xn);

    // 2. qkv projection (tf32 GEMM, scatter epilogue, q scale)
    tg_nn(xn, w_qkv, nullptr, q, BN, 1536, DIM, DIM, 1536, 0, 0,
          0, 0, 0, 0, 1, 1.f, 0.f, 0.f, 1, nullptr, nullptr, k, v);

    // 3. landmarks
    k_landmark<<<(int)(SZ_L / 256), 256>>>(q, k, ql, kl);

    // 4. similarity GEMMs (NT, K=64)
    tg_nt(q,  kl, nullptr, a1, Nn, Mm, DHd, DHd, DHd, 0, Mm,
          sQ, sL, 0, sA1, BH, 1.f, 0.f, 0.f);
    tg_nt(ql, kl, nullptr, a2, Mm, Mm, DHd, DHd, DHd, 0, Mm,
          sL, sL, 0, s2, BH, 1.f, 0.f, 0.f);
    tg_nt(ql, k,  nullptr, a3, Mm, Nn, DHd, DHd, DHd, 0, Nn,
          sL, sQ, 0, (long long)Mm * Nn, BH, 1.f, 0.f, 0.f);

    // 5. softmaxes (in place)
    k_softmax<<<BH * Nn, 256>>>(a1, Mm);
    k_softmax<<<BH * Mm, 256>>>(a2, Mm);
    k_softmax<<<BH * Mm, 256>>>(a3, Nn);

    // 6. pinv init: z = a2^T / (max(rowsum) * max(colsum))
    k_reset_scal<<<1, 32>>>(scal);
    k_rowmax<<<BH * Mm, 256>>>(a2, scal);
    k_colmax<<<BH, 256>>>(a2, scal);
    k_zinit<<<(int)(SZ_A2 / 256), 256>>>(a2, zA, scal);

    // 7. Newton-Schulz iterations (6), batched 256^3 tf32 GEMMs
    float* zc = zA; float* zn = zB;
    for (int it = 0; it < 6; it++) {
        tg_nn(a2, zc, nullptr, P, Mm, Mm, Mm, Mm, Mm, 0, Mm,
              s2, s2, 0, s2, BH, 1.f, 0.f, 0.f);
        tg_nn(P, P, P, S, Mm, Mm, Mm, Mm, Mm, Mm, Mm,
              s2, s2, s2, s2, BH, 1.f, -7.f, 15.f);
        tg_nn(P, S, nullptr, U, Mm, Mm, Mm, Mm, Mm, 0, Mm,
              s2, s2, 0, s2, BH, -1.f, 0.f, 13.f);
        tg_nn(zc, U, nullptr, zn, Mm, Mm, Mm, Mm, Mm, 0, Mm,
              s2, s2, 0, s2, BH, 0.25f, 0.f, 0.f);
        float* tmp = zc; zc = zn; zn = tmp;
    }

    // 8. a3v = a3 @ v   [256 x 64, K=4096]
    tg_nn64(a3, v, a3v, Mm, Nn, Nn, DHd, DHd,
            (long long)Mm * Nn, sQ, sL, BH, 0);

    // 9. a1z = a1 @ z   [N x M]   (into a3's buffer)
    tg_nn(a1, zc, nullptr, a1z, Nn, Mm, Mm, Mm, Mm, 0, Mm,
          sA1, s2, 0, sA1, BH, 1.f, 0.f, 0.f);

    // 10. outg = gathered(a1z @ a3v)  (epi 3 head-scatter into [BN][DIM])
    tg_nn64(a1z, a3v, outg, Nn, Mm, Mm, DHd, DIM,
            sA1, sL, 0, BH, 3);

    // 11. residual depthwise conv (adds into gathered layout)
    k_conv<<<dim3(Nn / 64, BH), 256>>>(v, res_w, outg);

    // 12. final: out = x + outg @ w_out + b_out   (epi 2)
    tg_nn(outg, w_out, nullptr, out, BN, DIM, DIM, DIM, DIM, 0, DIM,
          0, 0, 0, 0, 1, 1.f, 0.f, 0.f, 2, b_out, x, nullptr, nullptr);
}

// round 6
// speedup vs baseline: 2.1486x; 1.1005x over previous
#include <cuda_runtime.h>
#include <cstdint>
#include <cstddef>

// ---------------------------------------------------------------------------
// Problem constants
// ---------------------------------------------------------------------------
constexpr int Bb   = 4;
constexpr int Nn   = 4096;
constexpr int DIM  = 512;
constexpr int Hh   = 8;
constexpr int DHd  = 64;
constexpr int Mm   = 256;       // landmarks
constexpr int LMr  = 16;        // tokens per landmark  (N / M)
constexpr int BH   = Bb * Hh;   // 32
constexpr int BN   = Bb * Nn;   // 16384
constexpr int KCONV = 33;

// ---------------------------------------------------------------------------
// Scratch layout (single __device__ buffer, offsets in floats). ~460 MB.
// outg (gathered out-heads) aliases xn; a1z aliases a3.
// ---------------------------------------------------------------------------
constexpr size_t SZ_XN  = (size_t)BN * DIM;        // 8388608
constexpr size_t SZ_HND = (size_t)BH * Nn * DHd;   // 8388608
constexpr size_t SZ_L   = (size_t)BH * Mm * DHd;   // 524288
constexpr size_t SZ_A1  = (size_t)BH * Nn * Mm;    // 33554432
constexpr size_t SZ_A2  = (size_t)BH * Mm * Mm;    // 2097152

constexpr size_t OFF_XN   = 0;                     // xn, later reused as outg
constexpr size_t OFF_Q    = OFF_XN  + SZ_XN;
constexpr size_t OFF_K    = OFF_Q   + SZ_HND;
constexpr size_t OFF_V    = OFF_K   + SZ_HND;
constexpr size_t OFF_QL   = OFF_V   + SZ_HND;
constexpr size_t OFF_KL   = OFF_QL  + SZ_L;
constexpr size_t OFF_A1   = OFF_KL  + SZ_L;
constexpr size_t OFF_A3   = OFF_A1  + SZ_A1;       // a3, later reused as a1z
constexpr size_t OFF_A2   = OFF_A3  + SZ_A1;
constexpr size_t OFF_ZA   = OFF_A2  + SZ_A2;
constexpr size_t OFF_ZB   = OFF_ZA  + SZ_A2;
constexpr size_t OFF_P    = OFF_ZB  + SZ_A2;
constexpr size_t OFF_S    = OFF_P   + SZ_A2;
constexpr size_t OFF_U    = OFF_S   + SZ_A2;
constexpr size_t OFF_A3V  = OFF_U   + SZ_A2;
constexpr size_t OFF_SCAL = OFF_A3V + SZ_L;
constexpr size_t TOTAL_F  = OFF_SCAL + 16;

__device__ float g_buf[TOTAL_F];

// ---------------------------------------------------------------------------
// tf32 helpers
// ---------------------------------------------------------------------------
__device__ __forceinline__ float to_tf32(float f) {
    uint32_t u;
    asm("cvt.rna.tf32.f32 %0, %1;" : "=r"(u) : "f"(f));
    return __uint_as_float(u);
}

__device__ __forceinline__ void mma_tf32(float* c, const uint4& a, const uint2& b) {
    asm volatile(
        "mma.sync.aligned.m16n8k8.row.col.f32.tf32.tf32.f32 "
        "{%0,%1,%2,%3}, {%4,%5,%6,%7}, {%8,%9}, {%0,%1,%2,%3};\n"
        : "+f"(c[0]), "+f"(c[1]), "+f"(c[2]), "+f"(c[3])
        : "r"(a.x), "r"(a.y), "r"(a.z), "r"(a.w), "r"(b.x), "r"(b.y));
}

// ---------------------------------------------------------------------------
// Tensor-core tf32 GEMM.
//   C = alpha*(A @ B(^T)) + beta*D + diag*I     (epi 0, per batch z)
//   epi 1: qkv scatter (C=q, e3=k, e4=v), q scaled 0.125
//   epi 2: C = acc + e1[col] + e2[row*ldc+col]     (bias + residual)
//   epi 3: head-scatter: C[(b*Nn+r)*DIM + h*64 + c], bh = blockIdx.z
// BM x BNt block tile, BK=16, 256 threads (8 warps), warp tile WM x WN.
// SMEM fragment-major layout with XOR swizzles; double buffered.
// ---------------------------------------------------------------------------
template<int BM, int BNt, int WM, int WN, bool TB>
__global__ __launch_bounds__(256)
void tgemm(const float* __restrict__ A, const float* __restrict__ B,
           const float* __restrict__ D, float* __restrict__ C,
           int K, int lda, int ldb, int ldd, int ldc,
           long long sA, long long sB, long long sD, long long sC,
           float alpha, float beta, float diag,
           int epi, const float* __restrict__ e1, const float* __restrict__ e2,
           float* __restrict__ e3, float* __restrict__ e4)
{
    constexpr int MT  = WM / 16;          // m16 tiles per warp
    constexpr int NTn = WN / 8;           // n8 tiles per warp
    constexpr int WCOLS = BNt / WN;
    constexpr int ATILES = BM / 16;       // m tiles per block
    constexpr int BTILES = BNt / 8;       // n tiles per block
    constexpr int ASZ = 2 * ATILES * 128; // floats per buffer (2 k-tiles)
    constexpr int BSZ = 2 * BTILES * 64;
    constexpr int AQ = BM / 64;           // float4 loads per thread (A chunk)
    constexpr int BQ = BNt / 64;
    static_assert((BM / WM) * WCOLS == 8, "8 warps");

    __shared__ float As[2][ASZ];
    __shared__ float Bs[2][BSZ];

    int tid = threadIdx.x, lane = tid & 31, warp = tid >> 5;
    int wm = warp / WCOLS, wn = warp % WCOLS;
    int bz = blockIdx.z;
    int m0 = blockIdx.y * BM, n0 = blockIdx.x * BNt;
    const float* Ap = A + (size_t)bz * sA;
    const float* Bp = B + (size_t)bz * sB;

    float acc[MT][NTn][4];
    #pragma unroll
    for (int i = 0; i < MT; i++)
        #pragma unroll
        for (int j = 0; j < NTn; j++)
            #pragma unroll
            for (int r = 0; r < 4; r++) acc[i][j][r] = 0.f;

    // fragment-major store helpers (with bank-conflict XOR swizzles)
    auto stA = [&](int buf, int m, int kk, float val) {
        int mtile = m >> 4, mloc = m & 15;
        int ktile = kk >> 3, kloc = kk & 7;
        int la = ((mloc & 7) << 2) | (kloc & 3);
        la ^= (la >> 3) & 3;
        int reg = (mloc >> 3) | ((kloc >> 2) << 1);
        As[buf][(ktile * ATILES + mtile) * 128 + la * 4 + reg] = val;
    };
    auto stB = [&](int buf, int kk, int n, float val) {
        int ntile = n >> 3, nloc = n & 7;
        int ktile = kk >> 3, kloc = kk & 7;
        int lb = (nloc << 2) | (kloc & 3);
        lb ^= ((ntile & 3) << 2) | ((ntile >> 2) & 3);
        int reg = kloc >> 2;
        Bs[buf][(ktile * BTILES + ntile) * 64 + lb * 2 + reg] = val;
    };

    auto ldgA = [&](int kt, float4* pr) {
        #pragma unroll
        for (int i = 0; i < AQ; i++) {
            int q = i * 256 + tid;
            int m = q >> 2, kq = (q & 3) << 2;
            pr[i] = *(const float4*)(Ap + (size_t)(m0 + m) * lda + kt + kq);
        }
    };
    auto cmtA = [&](int buf, const float4* pr) {
        #pragma unroll
        for (int i = 0; i < AQ; i++) {
            int q = i * 256 + tid;
            int m = q >> 2, kq = (q & 3) << 2;
            stA(buf, m, kq + 0, to_tf32(pr[i].x));
            stA(buf, m, kq + 1, to_tf32(pr[i].y));
            stA(buf, m, kq + 2, to_tf32(pr[i].z));
            stA(buf, m, kq + 3, to_tf32(pr[i].w));
        }
    };
    auto ldgB = [&](int kt, float4* pr) {
        #pragma unroll
        for (int i = 0; i < BQ; i++) {
            int q = i * 256 + tid;
            if (!TB) {
                int kk = q / (BNt / 4), n = (q % (BNt / 4)) * 4;
                pr[i] = *(const float4*)(Bp + (size_t)(kt + kk) * ldb + n0 + n);
            } else {
                int n = q >> 2, kq = (q & 3) << 2;
                pr[i] = *(const float4*)(Bp + (size_t)(n0 + n) * ldb + kt + kq);
            }
        }
    };
    auto cmtB = [&](int buf, const float4* pr) {
        #pragma unroll
        for (int i = 0; i < BQ; i++) {
            int q = i * 256 + tid;
            if (!TB) {
                int kk = q / (BNt / 4), n = (q % (BNt / 4)) * 4;
                stB(buf, kk, n + 0, to_tf32(pr[i].x));
                stB(buf, kk, n + 1, to_tf32(pr[i].y));
                stB(buf, kk, n + 2, to_tf32(pr[i].z));
                stB(buf, kk, n + 3, to_tf32(pr[i].w));
            } else {
                int n = q >> 2, kq = (q & 3) << 2;
                stB(buf, kq + 0, n, to_tf32(pr[i].x));
                stB(buf, kq + 1, n, to_tf32(pr[i].y));
                stB(buf, kq + 2, n, to_tf32(pr[i].z));
                stB(buf, kq + 3, n, to_tf32(pr[i].w));
            }
        }
    };

    int nch = K >> 4;
    float4 pa[AQ], pb[BQ];
    ldgA(0, pa); ldgB(0, pb);
    cmtA(0, pa); cmtB(0, pb);
    __syncthreads();

    int buf = 0;
    int laAddr = (lane ^ ((lane >> 3) & 3)) * 4;
    for (int c = 0; c < nch; c++) {
        bool more = (c + 1 < nch);
        if (more) { ldgA((c + 1) << 4, pa); ldgB((c + 1) << 4, pb); }
        #pragma unroll
        for (int ks = 0; ks < 2; ks++) {
            uint4 af[MT]; uint2 bf[NTn];
            #pragma unroll
            for (int mt = 0; mt < MT; mt++)
                af[mt] = *(const uint4*)&As[buf][(ks * ATILES + wm * MT + mt) * 128 + laAddr];
            #pragma unroll
            for (int nt = 0; nt < NTn; nt++) {
                int ntile = wn * NTn + nt;
                int swz = ((ntile & 3) << 2) | ((ntile >> 2) & 3);
                bf[nt] = *(const uint2*)&Bs[buf][(ks * BTILES + ntile) * 64 + (lane ^ swz) * 2];
            }
            #pragma unroll
            for (int mt = 0; mt < MT; mt++)
                #pragma unroll
                for (int nt = 0; nt < NTn; nt++)
                    mma_tf32(acc[mt][nt], af[mt], bf[nt]);
        }
        if (more) { cmtA(buf ^ 1, pa); cmtB(buf ^ 1, pb); __syncthreads(); buf ^= 1; }
    }

    // epilogue
    int rw = m0 + wm * WM;
    int cw = n0 + wn * WN;
    bool hasD = (D != nullptr);
    #pragma unroll
    for (int mt = 0; mt < MT; mt++) {
        #pragma unroll
        for (int nt = 0; nt < NTn; nt++) {
            int rbase = rw + mt * 16 + (lane >> 2);
            int cc = cw + nt * 8 + (lane & 3) * 2;
            const float* a4 = acc[mt][nt];
            #pragma unroll
            for (int half = 0; half < 2; half++) {
                int rr = rbase + half * 8;
                float v0 = a4[half * 2 + 0], v1 = a4[half * 2 + 1];
                if (epi == 0) {
                    v0 *= alpha; v1 *= alpha;
                    if (hasD) {
                        size_t od = (size_t)bz * sD + (size_t)rr * ldd + cc;
                        v0 += beta * D[od];
                        v1 += beta * D[od + 1];
                    }
                    if (rr == cc)     v0 += diag;
                    if (rr == cc + 1) v1 += diag;
                    size_t oc = (size_t)bz * sC + (size_t)rr * ldc + cc;
                    C[oc] = v0; C[oc + 1] = v1;
                } else if (epi == 1) {
                    int bidx = rr >> 12, n = rr & (Nn - 1);
                    #pragma unroll
                    for (int u = 0; u < 2; u++) {
                        int c1 = cc + u;
                        float val = u ? v1 : v0;
                        int which = c1 >> 9, hc = (c1 >> 6) & 7, d = c1 & 63;
                        size_t dst = (((size_t)bidx * Hh + hc) * Nn + n) * DHd + d;
                        if (which == 0)      C[dst]  = val * 0.125f;
                        else if (which == 1) e3[dst] = val;
                        else                 e4[dst] = val;
                    }
                } else if (epi == 2) {
                    size_t o = (size_t)rr * ldc;
                    C[o + cc]     = v0 + e1[cc]     + e2[o + cc];
                    C[o + cc + 1] = v1 + e1[cc + 1] + e2[o + cc + 1];
                } else {   // epi 3: head scatter (bz = bh)
                    int b = bz >> 3, h = bz & 7;
                    size_t o = ((size_t)(b * Nn + rr)) * DIM + h * DHd;
                    C[o + cc] = v0; C[o + cc + 1] = v1;
                }
            }
        }
    }
}

// ---------------------------------------------------------------------------
// LayerNorm
// ---------------------------------------------------------------------------
__global__ __launch_bounds__(128)
void k_layernorm(const float* __restrict__ x, const float* __restrict__ w,
                 const float* __restrict__ b, float* __restrict__ y)
{
    int row = blockIdx.x, t = threadIdx.x;
    const float4* xp = (const float4*)(x + (size_t)row * DIM);
    float4 xv = xp[t];
    float s  = xv.x + xv.y + xv.z + xv.w;
    float ss = xv.x*xv.x + xv.y*xv.y + xv.z*xv.z + xv.w*xv.w;
    __shared__ float rs[128], rq[128];
    rs[t] = s; rq[t] = ss;
    __syncthreads();
    for (int o = 64; o > 0; o >>= 1) {
        if (t < o) { rs[t] += rs[t+o]; rq[t] += rq[t+o]; }
        __syncthreads();
    }
    float mean = rs[0] * (1.0f / DIM);
    float var  = rq[0] * (1.0f / DIM) - mean * mean;
    float inv  = rsqrtf(var + 1e-5f);
    float4 wv = ((const float4*)w)[t];
    float4 bv = ((const float4*)b)[t];
    float4 o4;
    o4.x = (xv.x - mean) * inv * wv.x + bv.x;
    o4.y = (xv.y - mean) * inv * wv.y + bv.y;
    o4.z = (xv.z - mean) * inv * wv.z + bv.z;
    o4.w = (xv.w - mean) * inv * wv.w + bv.w;
    ((float4*)(y + (size_t)row * DIM))[t] = o4;
}

// ---------------------------------------------------------------------------
// Landmark means
// ---------------------------------------------------------------------------
__global__ __launch_bounds__(256)
void k_landmark(const float* __restrict__ q, const float* __restrict__ k,
                float* __restrict__ ql, float* __restrict__ kl)
{
    int g = blockIdx.x * 256 + threadIdx.x;
    int d  = g & 63;
    int m  = (g >> 6) & (Mm - 1);
    int bh = g >> 14;
    size_t base = ((size_t)bh * Nn + m * LMr) * DHd + d;
    float sq = 0.f, sk = 0.f;
    #pragma unroll
    for (int j = 0; j < LMr; j++) {
        sq += q[base + (size_t)j * DHd];
        sk += k[base + (size_t)j * DHd];
    }
    ql[g] = sq * (1.0f / LMr);
    kl[g] = sk * (1.0f / LMr);
}

// ---------------------------------------------------------------------------
// Softmax, warp-per-row, L=256 (8 rows per 256-thread block, no barriers)
// ---------------------------------------------------------------------------
__global__ __launch_bounds__(256)
void k_softmax256(float* __restrict__ X)
{
    int warp = threadIdx.x >> 5, lane = threadIdx.x & 31;
    size_t row = (size_t)blockIdx.x * 8 + warp;
    float4* p = (float4*)(X + row * 256);
    float4 a = p[lane];
    float4 b = p[lane + 32];
    float mx = fmaxf(fmaxf(fmaxf(a.x, a.y), fmaxf(a.z, a.w)),
                     fmaxf(fmaxf(b.x, b.y), fmaxf(b.z, b.w)));
    #pragma unroll
    for (int o = 16; o > 0; o >>= 1)
        mx = fmaxf(mx, __shfl_xor_sync(0xffffffffu, mx, o));
    a.x = __expf(a.x - mx); a.y = __expf(a.y - mx);
    a.z = __expf(a.z - mx); a.w = __expf(a.w - mx);
    b.x = __expf(b.x - mx); b.y = __expf(b.y - mx);
    b.z = __expf(b.z - mx); b.w = __expf(b.w - mx);
    float s = a.x + a.y + a.z + a.w + b.x + b.y + b.z + b.w;
    #pragma unroll
    for (int o = 16; o > 0; o >>= 1)
        s += __shfl_xor_sync(0xffffffffu, s, o);
    float inv = 1.0f / s;
    a.x *= inv; a.y *= inv; a.z *= inv; a.w *= inv;
    b.x *= inv; b.y *= inv; b.z *= inv; b.w *= inv;
    p[lane] = a;
    p[lane + 32] = b;
}

// ---------------------------------------------------------------------------
// Softmax, block-per-row, L=4096 (shuffle + 2-barrier reduction)
// ---------------------------------------------------------------------------
__global__ __launch_bounds__(256)
void k_softmax4096(float* __restrict__ X)
{
    int t = threadIdx.x, lane = t & 31, warp = t >> 5;
    float4* p = (float4*)(X + (size_t)blockIdx.x * 4096);
    float4 v[4];
    float mx = -1e30f;
    #pragma unroll
    for (int i = 0; i < 4; i++) {
        v[i] = p[t + (i << 8)];
        mx = fmaxf(mx, fmaxf(fmaxf(v[i].x, v[i].y), fmaxf(v[i].z, v[i].w)));
    }
    __shared__ float red[8];
    #pragma unroll
    for (int o = 16; o > 0; o >>= 1)
        mx = fmaxf(mx, __shfl_xor_sync(0xffffffffu, mx, o));
    if (lane == 0) red[warp] = mx;
    __syncthreads();
    mx = red[lane & 7];
    #pragma unroll
    for (int o = 4; o > 0; o >>= 1)
        mx = fmaxf(mx, __shfl_xor_sync(0xffffffffu, mx, o));
    float s = 0.f;
    #pragma unroll
    for (int i = 0; i < 4; i++) {
        v[i].x = __expf(v[i].x - mx); v[i].y = __expf(v[i].y - mx);
        v[i].z = __expf(v[i].z - mx); v[i].w = __expf(v[i].w - mx);
        s += v[i].x + v[i].y + v[i].z + v[i].w;
    }
    #pragma unroll
    for (int o = 16; o > 0; o >>= 1)
        s += __shfl_xor_sync(0xffffffffu, s, o);
    __syncthreads();
    if (lane == 0) red[warp] = s;
    __syncthreads();
    s = red[lane & 7];
    #pragma unroll
    for (int o = 4; o > 0; o >>= 1)
        s += __shfl_xor_sync(0xffffffffu, s, o);
    float inv = 1.0f / s;
    #pragma unroll
    for (int i = 0; i < 4; i++) {
        v[i].x *= inv; v[i].y *= inv; v[i].z *= inv; v[i].w *= inv;
        p[t + (i << 8)] = v[i];
    }
}

// ---------------------------------------------------------------------------
// pinv init scalars
// ---------------------------------------------------------------------------
__global__ void k_reset_scal(float* scal) { if (threadIdx.x < 2) scal[threadIdx.x] = 0.f; }

__global__ __launch_bounds__(256)
void k_rowmax(const float* __restrict__ a2, float* scal)
{
    int row = blockIdx.x, t = threadIdx.x;
    float v = a2[(size_t)row * Mm + t];
    __shared__ float red[256];
    red[t] = v; __syncthreads();
    for (int o = 128; o > 0; o >>= 1) { if (t < o) red[t] += red[t+o]; __syncthreads(); }
    if (t == 0) atomicMax((unsigned*)&scal[0], __float_as_uint(red[0]));
}

__global__ __launch_bounds__(256)
void k_colmax(const float* __restrict__ a2, float* scal)
{
    int bh = blockIdx.x, j = threadIdx.x;
    const float* p = a2 + ((size_t)bh << 16) + j;
    float s = 0.f;
    for (int i = 0; i < Mm; i++) s += p[(size_t)i * Mm];
    __shared__ float red[256];
    red[j] = s; __syncthreads();
    for (int o = 128; o > 0; o >>= 1) { if (j < o) red[j] = fmaxf(red[j], red[j+o]); __syncthreads(); }
    if (j == 0) atomicMax((unsigned*)&scal[1], __float_as_uint(red[0]));
}

__global__ __launch_bounds__(256)
void k_zinit(const float* __restrict__ a2, float* __restrict__ z, const float* scal)
{
    int g = blockIdx.x * 256 + threadIdx.x;
    float inv = 1.0f / (scal[0] * scal[1]);
    int j = g & 255, i = (g >> 8) & 255, bh = g >> 16;
    z[g] = a2[((size_t)bh << 16) + (size_t)j * Mm + i] * inv;
}

// ---------------------------------------------------------------------------
// Depthwise residual conv over sequence: outg(gathered) += conv33(v)
// ---------------------------------------------------------------------------
__global__ __launch_bounds__(256)
void k_conv(const float* __restrict__ v, const float* __restrict__ rw,
            float* __restrict__ outg)
{
    int bh = blockIdx.y;
    int b = bh >> 3, h = bh & 7;
    int n0 = blockIdx.x * 64;
    __shared__ float vs[96][64];
    __shared__ float ws[KCONV];
    int t = threadIdx.x;
    const float* vp = v + (size_t)bh * Nn * DHd;
    for (int idx = t; idx < 96 * 64; idx += 256) {
        int r = idx >> 6, d = idx & 63;
        int n = n0 - 16 + r;
        vs[r][d] = (n >= 0 && n < Nn) ? vp[(size_t)n * DHd + d] : 0.0f;
    }
    if (t < KCONV) ws[t] = rw[h * KCONV + t];
    __syncthreads();
    int d = t & 63, r0 = t >> 6;
    for (int nn = r0; nn < 64; nn += 4) {
        float acc = 0.f;
        #pragma unroll
        for (int tt = 0; tt < KCONV; tt++)
            acc = fmaf(ws[tt], vs[nn + tt][d], acc);
        outg[((size_t)(b * Nn + n0 + nn)) * DIM + h * DHd + d] += acc;
    }
}

// ---------------------------------------------------------------------------
// Host-side launch helpers (4 tgemm instantiations)
// ---------------------------------------------------------------------------
static inline void tg_nn(const float* A, const float* B, const float* D, float* C,
                         int M, int N, int K, int lda, int ldb, int ldd, int ldc,
                         long long sA, long long sB, long long sD, long long sC,
                         int batch, float alpha, float beta, float diag,
                         int epi = 0, const float* e1 = nullptr, const float* e2 = nullptr,
                         float* e3 = nullptr, float* e4 = nullptr)
{
    tgemm<128,128,64,32,false><<<dim3(N/128, M/128, batch), 256>>>(
        A, B, D, C, K, lda, ldb, ldd, ldc, sA, sB, sD, sC,
        alpha, beta, diag, epi, e1, e2, e3, e4);
}
static inline void tg_nt(const float* A, const float* B, const float* D, float* C,
                         int M, int N, int K, int lda, int ldb, int ldd, int ldc,
                         long long sA, long long sB, long long sD, long long sC,
                         int batch, float alpha, float beta, float diag)
{
    tgemm<128,128,64,32,true><<<dim3(N/128, M/128, batch), 256>>>(
        A, B, D, C, K, lda, ldb, ldd, ldc, sA, sB, sD, sC,
        alpha, beta, diag, 0, nullptr, nullptr, nullptr, nullptr);
}
// 128x64 tile variant (N=64 outg GEMM, M large)
static inline void tg_nn64(const float* A, const float* B, float* C,
                           int M, int K, int lda, int ldb, int ldc,
                           long long sA, long long sB, long long sC,
                           int batch, int epi)
{
    tgemm<128,64,32,32,false><<<dim3(1, M/128, batch), 256>>>(
        A, B, nullptr, C, K, lda, ldb, 0, ldc, sA, sB, 0, sC,
        1.f, 0.f, 0.f, epi, nullptr, nullptr, nullptr, nullptr);
}
// 64x64 tile variant: high-occupancy small GEMMs (pinv 256^3, a3v)
static inline void tg_sm(const float* A, const float* B, const float* D, float* C,
                         int M, int N, int K, int lda, int ldb, int ldd, int ldc,
                         long long sA, long long sB, long long sD, long long sC,
                         int batch, float alpha, float beta, float diag)
{
    tgemm<64,64,32,16,false><<<dim3(N/64, M/64, batch), 256>>>(
        A, B, D, C, K, lda, ldb, ldd, ldc, sA, sB, sD, sC,
        alpha, beta, diag, 0, nullptr, nullptr, nullptr, nullptr);
}

extern "C" void kernel_launch(void* const* d_in, const int* in_sizes, int n_in,
                              void* d_out, int out_size)
{
    const float* x      = (const float*)d_in[0];
    const float* norm_w = (const float*)d_in[1];
    const float* norm_b = (const float*)d_in[2];
    const float* w_qkv  = (const float*)d_in[3];
    const float* w_out  = (const float*)d_in[4];
    const float* b_out  = (const float*)d_in[5];
    const float* res_w  = (const float*)d_in[6];
    float* out = (float*)d_out;

    float* buf = nullptr;
    cudaGetSymbolAddress((void**)&buf, g_buf);

    float* xn   = buf + OFF_XN;
    float* q    = buf + OFF_Q;
    float* k    = buf + OFF_K;
    float* v    = buf + OFF_V;
    float* ql   = buf + OFF_QL;
    float* kl   = buf + OFF_KL;
    float* a1   = buf + OFF_A1;
    float* a3   = buf + OFF_A3;
    float* a2   = buf + OFF_A2;
    float* zA   = buf + OFF_ZA;
    float* zB   = buf + OFF_ZB;
    float* P    = buf + OFF_P;
    float* S    = buf + OFF_S;
    float* U    = buf + OFF_U;
    float* a3v  = buf + OFF_A3V;
    float* scal = buf + OFF_SCAL;
    float* a1z  = a3;   // reuse (a3 dead after a3v GEMM)
    float* outg = xn;   // reuse (xn dead after qkv GEMM); gathered [BN][DIM]

    const long long sQ = (long long)Nn * DHd, sL = (long long)Mm * DHd;
    const long long s2 = (long long)Mm * Mm;
    const long long sA1 = (long long)Nn * Mm;

    // 1. LayerNorm
    k_layernorm<<<BN, 128>>>(x, norm_w, norm_b, xn);

    // 2. qkv projection (tf32 GEMM, scatter epilogue, q scale)
    tg_nn(xn, w_qkv, nullptr, q, BN, 1536, DIM, DIM, 1536, 0, 0,
          0, 0, 0, 0, 1, 1.f, 0.f, 0.f, 1, nullptr, nullptr, k, v);

    // 3. landmarks
    k_landmark<<<(int)(SZ_L / 256), 256>>>(q, k, ql, kl);

    // 4. similarity GEMMs (NT, K=64)
    tg_nt(q,  kl, nullptr, a1, Nn, Mm, DHd, DHd, DHd, 0, Mm,
          sQ, sL, 0, sA1, BH, 1.f, 0.f, 0.f);
    tg_nt(ql, kl, nullptr, a2, Mm, Mm, DHd, DHd, DHd, 0, Mm,
          sL, sL, 0, s2, BH, 1.f, 0.f, 0.f);
    tg_nt(ql, k,  nullptr, a3, Mm, Nn, DHd, DHd, DHd, 0, Nn,
          sL, sQ, 0, (long long)Mm * Nn, BH, 1.f, 0.f, 0.f);

    // 5. softmaxes (in place)
    k_softmax256<<<BH * Nn / 8, 256>>>(a1);
    k_softmax256<<<BH * Mm / 8, 256>>>(a2);
    k_softmax4096<<<BH * Mm, 256>>>(a3);

    // 6. pinv init: z = a2^T / (max(rowsum) * max(colsum))
    k_reset_scal<<<1, 32>>>(scal);
    k_rowmax<<<BH * Mm, 256>>>(a2, scal);
    k_colmax<<<BH, 256>>>(a2, scal);
    k_zinit<<<(int)(SZ_A2 / 256), 256>>>(a2, zA, scal);

    // 7. Newton-Schulz iterations (6), batched 256^3 tf32 GEMMs (64x64 tiles,
    //    512 CTAs/launch for occupancy on the serial chain)
    float* zc = zA; float* zn = zB;
    for (int it = 0; it < 6; it++) {
        tg_sm(a2, zc, nullptr, P, Mm, Mm, Mm, Mm, Mm, 0, Mm,
              s2, s2, 0, s2, BH, 1.f, 0.f, 0.f);
        tg_sm(P, P, P, S, Mm, Mm, Mm, Mm, Mm, Mm, Mm,
              s2, s2, s2, s2, BH, 1.f, -7.f, 15.f);
        tg_sm(P, S, nullptr, U, Mm, Mm, Mm, Mm, Mm, 0, Mm,
              s2, s2, 0, s2, BH, -1.f, 0.f, 13.f);
        tg_sm(zc, U, nullptr, zn, Mm, Mm, Mm, Mm, Mm, 0, Mm,
              s2, s2, 0, s2, BH, 0.25f, 0.f, 0.f);
        float* tmp = zc; zc = zn; zn = tmp;
    }

    // 8. a3v = a3 @ v   [256 x 64, K=4096]  (64x64 tiles -> 128 CTAs)
    tg_sm(a3, v, nullptr, a3v, Mm, DHd, Nn, Nn, DHd, 0, DHd,
          (long long)Mm * Nn, sQ, 0, sL, BH, 1.f, 0.f, 0.f);

    // 9. a1z = a1 @ z   [N x M]   (into a3's buffer)
    tg_nn(a1, zc, nullptr, a1z, Nn, Mm, Mm, Mm, Mm, 0, Mm,
          sA1, s2, 0, sA1, BH, 1.f, 0.f, 0.f);

    // 10. outg = gathered(a1z @ a3v)  (epi 3 head-scatter into [BN][DIM])
    tg_nn64(a1z, a3v, outg, Nn, Mm, Mm, DHd, DIM,
            sA1, sL, 0, BH, 3);

    // 11. residual depthwise conv (adds into gathered layout)
    k_conv<<<dim3(Nn / 64, BH), 256>>>(v, res_w, outg);

    // 12. final: out = x + outg @ w_out + b_out   (epi 2)
    tg_nn(outg, w_out, nullptr, out, BN, DIM, DIM, DIM, DIM, 0, DIM,
          0, 0, 0, 0, 1, 1.f, 0.f, 0.f, 2, b_out, x, nullptr, nullptr);
}

// round 8
// speedup vs baseline: 2.7011x; 1.2571x over previous
#include <cuda_runtime.h>
#include <cstdint>
#include <cstddef>

// ---------------------------------------------------------------------------
// Problem constants
// ---------------------------------------------------------------------------
constexpr int Bb   = 4;
constexpr int Nn   = 4096;
constexpr int DIM  = 512;
constexpr int Hh   = 8;
constexpr int DHd  = 64;
constexpr int Mm   = 256;       // landmarks
constexpr int LMr  = 16;        // tokens per landmark  (N / M)
constexpr int BH   = Bb * Hh;   // 32
constexpr int BN   = Bb * Nn;   // 16384
constexpr int KCONV = 33;

// ---------------------------------------------------------------------------
// Scratch layout (single __device__ buffer, offsets in floats). ~460 MB.
// outg aliases xn. (a1z is gone — associativity reorder.)
// ---------------------------------------------------------------------------
constexpr size_t SZ_XN  = (size_t)BN * DIM;
constexpr size_t SZ_HND = (size_t)BH * Nn * DHd;
constexpr size_t SZ_L   = (size_t)BH * Mm * DHd;
constexpr size_t SZ_A1  = (size_t)BH * Nn * Mm;
constexpr size_t SZ_A2  = (size_t)BH * Mm * Mm;

constexpr size_t OFF_XN   = 0;
constexpr size_t OFF_Q    = OFF_XN  + SZ_XN;
constexpr size_t OFF_K    = OFF_Q   + SZ_HND;
constexpr size_t OFF_V    = OFF_K   + SZ_HND;
constexpr size_t OFF_QL   = OFF_V   + SZ_HND;
constexpr size_t OFF_KL   = OFF_QL  + SZ_L;
constexpr size_t OFF_A1   = OFF_KL  + SZ_L;
constexpr size_t OFF_A3   = OFF_A1  + SZ_A1;
constexpr size_t OFF_A2   = OFF_A3  + SZ_A1;
constexpr size_t OFF_ZA   = OFF_A2  + SZ_A2;
constexpr size_t OFF_ZB   = OFF_ZA  + SZ_A2;
constexpr size_t OFF_P    = OFF_ZB  + SZ_A2;
constexpr size_t OFF_S    = OFF_P   + SZ_A2;
constexpr size_t OFF_U    = OFF_S   + SZ_A2;
constexpr size_t OFF_A3V  = OFF_U   + SZ_A2;
constexpr size_t OFF_W    = OFF_A3V + SZ_L;
constexpr size_t OFF_SCAL = OFF_W   + SZ_L;
constexpr size_t TOTAL_F  = OFF_SCAL + 16;

__device__ float g_buf[TOTAL_F];

// ---------------------------------------------------------------------------
// tf32 helpers
// ---------------------------------------------------------------------------
__device__ __forceinline__ float to_tf32(float f) {
    uint32_t u;
    asm("cvt.rna.tf32.f32 %0, %1;" : "=r"(u) : "f"(f));
    return __uint_as_float(u);
}

__device__ __forceinline__ void mma_tf32(float* c, const uint4& a, const uint2& b) {
    asm volatile(
        "mma.sync.aligned.m16n8k8.row.col.f32.tf32.tf32.f32 "
        "{%0,%1,%2,%3}, {%4,%5,%6,%7}, {%8,%9}, {%0,%1,%2,%3};\n"
        : "+f"(c[0]), "+f"(c[1]), "+f"(c[2]), "+f"(c[3])
        : "r"(a.x), "r"(a.y), "r"(a.z), "r"(a.w), "r"(b.x), "r"(b.y));
}

// ---------------------------------------------------------------------------
// Tensor-core tf32 GEMM (mma.sync). Thread count derived from tile config:
// THREADS = (BM/WM)*(BNt/WN)*32.
//   epi 0: C = alpha*(A@B(^T)) + beta*D + diag*I   (per batch z)
//   epi 1: qkv scatter (C=q, e3=k, e4=v), q scaled 0.125
//   epi 2: C = acc + e1[col] + e2[row*ldc+col]
//   epi 3: head-scatter: C[(b*Nn+r)*DIM + h*64 + c], bz = bh
// ---------------------------------------------------------------------------
template<int BM, int BNt, int WM, int WN, bool TB>
__global__ __launch_bounds__((BM/WM)*(BNt/WN)*32)
void tgemm(const float* __restrict__ A, const float* __restrict__ B,
           const float* __restrict__ D, float* __restrict__ C,
           int K, int lda, int ldb, int ldd, int ldc,
           long long sA, long long sB, long long sD, long long sC,
           float alpha, float beta, float diag,
           int epi, const float* __restrict__ e1, const float* __restrict__ e2,
           float* __restrict__ e3, float* __restrict__ e4)
{
    constexpr int MT  = WM / 16;
    constexpr int NTn = WN / 8;
    constexpr int WCOLS = BNt / WN;
    constexpr int NWP = (BM / WM) * (BNt / WN);
    constexpr int THREADS = NWP * 32;
    constexpr int ATILES = BM / 16;
    constexpr int BTILES = BNt / 8;
    constexpr int ASZ = 2 * ATILES * 128;
    constexpr int BSZ = 2 * BTILES * 64;
    constexpr int AQ = (BM * 16) / (THREADS * 4);
    constexpr int BQ = (BNt * 16) / (THREADS * 4);

    __shared__ float As[2][ASZ];
    __shared__ float Bs[2][BSZ];

    int tid = threadIdx.x, lane = tid & 31, warp = tid >> 5;
    int wm = warp / WCOLS, wn = warp % WCOLS;
    int bz = blockIdx.z;
    int m0 = blockIdx.y * BM, n0 = blockIdx.x * BNt;
    const float* Ap = A + (size_t)bz * sA;
    const float* Bp = B + (size_t)bz * sB;

    float acc[MT][NTn][4];
    #pragma unroll
    for (int i = 0; i < MT; i++)
        #pragma unroll
        for (int j = 0; j < NTn; j++)
            #pragma unroll
            for (int r = 0; r < 4; r++) acc[i][j][r] = 0.f;

    // fragment-major store helpers (bank-conflict XOR swizzles)
    auto stA = [&](int buf, int m, int kk, float val) {
        int mtile = m >> 4, mloc = m & 15;
        int ktile = kk >> 3, kloc = kk & 7;
        int la = ((mloc & 7) << 2) | (kloc & 3);
        la ^= (la >> 3) & 3;
        int reg = (mloc >> 3) | ((kloc >> 2) << 1);
        As[buf][(ktile * ATILES + mtile) * 128 + la * 4 + reg] = val;
    };
    auto stB = [&](int buf, int kk, int n, float val) {
        int ntile = n >> 3, nloc = n & 7;
        int ktile = kk >> 3, kloc = kk & 7;
        int lb = (nloc << 2) | (kloc & 3);
        lb ^= ((ntile & 3) << 2) | ((ntile >> 2) & 3);
        int reg = kloc >> 2;
        Bs[buf][(ktile * BTILES + ntile) * 64 + lb * 2 + reg] = val;
    };

    auto ldgA = [&](int kt, float4* pr) {
        #pragma unroll
        for (int i = 0; i < AQ; i++) {
            int q = i * THREADS + tid;
            int m = q >> 2, kq = (q & 3) << 2;
            pr[i] = *(const float4*)(Ap + (size_t)(m0 + m) * lda + kt + kq);
        }
    };
    auto cmtA = [&](int buf, const float4* pr) {
        #pragma unroll
        for (int i = 0; i < AQ; i++) {
            int q = i * THREADS + tid;
            int m = q >> 2, kq = (q & 3) << 2;
            stA(buf, m, kq + 0, to_tf32(pr[i].x));
            stA(buf, m, kq + 1, to_tf32(pr[i].y));
            stA(buf, m, kq + 2, to_tf32(pr[i].z));
            stA(buf, m, kq + 3, to_tf32(pr[i].w));
        }
    };
    auto ldgB = [&](int kt, float4* pr) {
        #pragma unroll
        for (int i = 0; i < BQ; i++) {
            int q = i * THREADS + tid;
            if (!TB) {
                int kk = q / (BNt / 4), n = (q % (BNt / 4)) * 4;
                pr[i] = *(const float4*)(Bp + (size_t)(kt + kk) * ldb + n0 + n);
            } else {
                int n = q >> 2, kq = (q & 3) << 2;
                pr[i] = *(const float4*)(Bp + (size_t)(n0 + n) * ldb + kt + kq);
            }
        }
    };
    auto cmtB = [&](int buf, const float4* pr) {
        #pragma unroll
        for (int i = 0; i < BQ; i++) {
            int q = i * THREADS + tid;
            if (!TB) {
                int kk = q / (BNt / 4), n = (q % (BNt / 4)) * 4;
                stB(buf, kk, n + 0, to_tf32(pr[i].x));
                stB(buf, kk, n + 1, to_tf32(pr[i].y));
                stB(buf, kk, n + 2, to_tf32(pr[i].z));
                stB(buf, kk, n + 3, to_tf32(pr[i].w));
            } else {
                int n = q >> 2, kq = (q & 3) << 2;
                stB(buf, kq + 0, n, to_tf32(pr[i].x));
                stB(buf, kq + 1, n, to_tf32(pr[i].y));
                stB(buf, kq + 2, n, to_tf32(pr[i].z));
                stB(buf, kq + 3, n, to_tf32(pr[i].w));
            }
        }
    };

    int nch = K >> 4;
    float4 pa[AQ], pb[BQ];
    ldgA(0, pa); ldgB(0, pb);
    cmtA(0, pa); cmtB(0, pb);
    __syncthreads();

    int buf = 0;
    int laAddr = (lane ^ ((lane >> 3) & 3)) * 4;
    for (int c = 0; c < nch; c++) {
        bool more = (c + 1 < nch);
        if (more) { ldgA((c + 1) << 4, pa); ldgB((c + 1) << 4, pb); }
        #pragma unroll
        for (int ks = 0; ks < 2; ks++) {
            uint4 af[MT]; uint2 bf[NTn];
            #pragma unroll
            for (int mt = 0; mt < MT; mt++)
                af[mt] = *(const uint4*)&As[buf][(ks * ATILES + wm * MT + mt) * 128 + laAddr];
            #pragma unroll
            for (int nt = 0; nt < NTn; nt++) {
                int ntile = wn * NTn + nt;
                int swz = ((ntile & 3) << 2) | ((ntile >> 2) & 3);
                bf[nt] = *(const uint2*)&Bs[buf][(ks * BTILES + ntile) * 64 + (lane ^ swz) * 2];
            }
            #pragma unroll
            for (int mt = 0; mt < MT; mt++)
                #pragma unroll
                for (int nt = 0; nt < NTn; nt++)
                    mma_tf32(acc[mt][nt], af[mt], bf[nt]);
        }
        if (more) { cmtA(buf ^ 1, pa); cmtB(buf ^ 1, pb); __syncthreads(); buf ^= 1; }
    }

    // epilogue
    int rw = m0 + wm * WM;
    int cw = n0 + wn * WN;
    bool hasD = (D != nullptr);
    #pragma unroll
    for (int mt = 0; mt < MT; mt++) {
        #pragma unroll
        for (int nt = 0; nt < NTn; nt++) {
            int rbase = rw + mt * 16 + (lane >> 2);
            int cc = cw + nt * 8 + (lane & 3) * 2;
            const float* a4 = acc[mt][nt];
            #pragma unroll
            for (int half = 0; half < 2; half++) {
                int rr = rbase + half * 8;
                float v0 = a4[half * 2 + 0], v1 = a4[half * 2 + 1];
                if (epi == 0) {
                    v0 *= alpha; v1 *= alpha;
                    if (hasD) {
                        size_t od = (size_t)bz * sD + (size_t)rr * ldd + cc;
                        v0 += beta * D[od];
                        v1 += beta * D[od + 1];
                    }
                    if (rr == cc)     v0 += diag;
                    if (rr == cc + 1) v1 += diag;
                    size_t oc = (size_t)bz * sC + (size_t)rr * ldc + cc;
                    C[oc] = v0; C[oc + 1] = v1;
                } else if (epi == 1) {
                    int bidx = rr >> 12, n = rr & (Nn - 1);
                    #pragma unroll
                    for (int u = 0; u < 2; u++) {
                        int c1 = cc + u;
                        float val = u ? v1 : v0;
                        int which = c1 >> 9, hc = (c1 >> 6) & 7, d = c1 & 63;
                        size_t dst = (((size_t)bidx * Hh + hc) * Nn + n) * DHd + d;
                        if (which == 0)      C[dst]  = val * 0.125f;
                        else if (which == 1) e3[dst] = val;
                        else                 e4[dst] = val;
                    }
                } else if (epi == 2) {
                    size_t o = (size_t)rr * ldc;
                    C[o + cc]     = v0 + e1[cc]     + e2[o + cc];
                    C[o + cc + 1] = v1 + e1[cc + 1] + e2[o + cc + 1];
                } else {   // epi 3: head scatter (bz = bh)
                    int b = bz >> 3, h = bz & 7;
                    size_t o = ((size_t)(b * Nn + rr)) * DIM + h * DHd;
                    C[o + cc] = v0; C[o + cc + 1] = v1;
                }
            }
        }
    }
}

// ---------------------------------------------------------------------------
// LayerNorm
// ---------------------------------------------------------------------------
__global__ __launch_bounds__(128)
void k_layernorm(const float* __restrict__ x, const float* __restrict__ w,
                 const float* __restrict__ b, float* __restrict__ y)
{
    int row = blockIdx.x, t = threadIdx.x;
    const float4* xp = (const float4*)(x + (size_t)row * DIM);
    float4 xv = xp[t];
    float s  = xv.x + xv.y + xv.z + xv.w;
    float ss = xv.x*xv.x + xv.y*xv.y + xv.z*xv.z + xv.w*xv.w;
    __shared__ float rs[128], rq[128];
    rs[t] = s; rq[t] = ss;
    __syncthreads();
    for (int o = 64; o > 0; o >>= 1) {
        if (t < o) { rs[t] += rs[t+o]; rq[t] += rq[t+o]; }
        __syncthreads();
    }
    float mean = rs[0] * (1.0f / DIM);
    float var  = rq[0] * (1.0f / DIM) - mean * mean;
    float inv  = rsqrtf(var + 1e-5f);
    float4 wv = ((const float4*)w)[t];
    float4 bv = ((const float4*)b)[t];
    float4 o4;
    o4.x = (xv.x - mean) * inv * wv.x + bv.x;
    o4.y = (xv.y - mean) * inv * wv.y + bv.y;
    o4.z = (xv.z - mean) * inv * wv.z + bv.z;
    o4.w = (xv.w - mean) * inv * wv.w + bv.w;
    ((float4*)(y + (size_t)row * DIM))[t] = o4;
}

// ---------------------------------------------------------------------------
// Landmark means
// ---------------------------------------------------------------------------
__global__ __launch_bounds__(256)
void k_landmark(const float* __restrict__ q, const float* __restrict__ k,
                float* __restrict__ ql, float* __restrict__ kl)
{
    int g = blockIdx.x * 256 + threadIdx.x;
    int d  = g & 63;
    int m  = (g >> 6) & (Mm - 1);
    int bh = g >> 14;
    size_t base = ((size_t)bh * Nn + m * LMr) * DHd + d;
    float sq = 0.f, sk = 0.f;
    #pragma unroll
    for (int j = 0; j < LMr; j++) {
        sq += q[base + (size_t)j * DHd];
        sk += k[base + (size_t)j * DHd];
    }
    ql[g] = sq * (1.0f / LMr);
    kl[g] = sk * (1.0f / LMr);
}

// ---------------------------------------------------------------------------
// Softmax kernels
// ---------------------------------------------------------------------------
__global__ __launch_bounds__(256)
void k_softmax256(float* __restrict__ X)
{
    int warp = threadIdx.x >> 5, lane = threadIdx.x & 31;
    size_t row = (size_t)blockIdx.x * 8 + warp;
    float4* p = (float4*)(X + row * 256);
    float4 a = p[lane];
    float4 b = p[lane + 32];
    float mx = fmaxf(fmaxf(fmaxf(a.x, a.y), fmaxf(a.z, a.w)),
                     fmaxf(fmaxf(b.x, b.y), fmaxf(b.z, b.w)));
    #pragma unroll
    for (int o = 16; o > 0; o >>= 1)
        mx = fmaxf(mx, __shfl_xor_sync(0xffffffffu, mx, o));
    a.x = __expf(a.x - mx); a.y = __expf(a.y - mx);
    a.z = __expf(a.z - mx); a.w = __expf(a.w - mx);
    b.x = __expf(b.x - mx); b.y = __expf(b.y - mx);
    b.z = __expf(b.z - mx); b.w = __expf(b.w - mx);
    float s = a.x + a.y + a.z + a.w + b.x + b.y + b.z + b.w;
    #pragma unroll
    for (int o = 16; o > 0; o >>= 1)
        s += __shfl_xor_sync(0xffffffffu, s, o);
    float inv = 1.0f / s;
    a.x *= inv; a.y *= inv; a.z *= inv; a.w *= inv;
    b.x *= inv; b.y *= inv; b.z *= inv; b.w *= inv;
    p[lane] = a;
    p[lane + 32] = b;
}

__global__ __launch_bounds__(256)
void k_softmax4096(float* __restrict__ X)
{
    int t = threadIdx.x, lane = t & 31, warp = t >> 5;
    float4* p = (float4*)(X + (size_t)blockIdx.x * 4096);
    float4 v[4];
    float mx = -1e30f;
    #pragma unroll
    for (int i = 0; i < 4; i++) {
        v[i] = p[t + (i << 8)];
        mx = fmaxf(mx, fmaxf(fmaxf(v[i].x, v[i].y), fmaxf(v[i].z, v[i].w)));
    }
    __shared__ float red[8];
    #pragma unroll
    for (int o = 16; o > 0; o >>= 1)
        mx = fmaxf(mx, __shfl_xor_sync(0xffffffffu, mx, o));
    if (lane == 0) red[warp] = mx;
    __syncthreads();
    mx = red[lane & 7];
    #pragma unroll
    for (int o = 4; o > 0; o >>= 1)
        mx = fmaxf(mx, __shfl_xor_sync(0xffffffffu, mx, o));
    float s = 0.f;
    #pragma unroll
    for (int i = 0; i < 4; i++) {
        v[i].x = __expf(v[i].x - mx); v[i].y = __expf(v[i].y - mx);
        v[i].z = __expf(v[i].z - mx); v[i].w = __expf(v[i].w - mx);
        s += v[i].x + v[i].y + v[i].z + v[i].w;
    }
    #pragma unroll
    for (int o = 16; o > 0; o >>= 1)
        s += __shfl_xor_sync(0xffffffffu, s, o);
    __syncthreads();
    if (lane == 0) red[warp] = s;
    __syncthreads();
    s = red[lane & 7];
    #pragma unroll
    for (int o = 4; o > 0; o >>= 1)
        s += __shfl_xor_sync(0xffffffffu, s, o);
    float inv = 1.0f / s;
    #pragma unroll
    for (int i = 0; i < 4; i++) {
        v[i].x *= inv; v[i].y *= inv; v[i].z *= inv; v[i].w *= inv;
        p[t + (i << 8)] = v[i];
    }
}

// ---------------------------------------------------------------------------
// pinv init scalars
// ---------------------------------------------------------------------------
__global__ void k_reset_scal(float* scal) { if (threadIdx.x < 2) scal[threadIdx.x] = 0.f; }

__global__ __launch_bounds__(256)
void k_rowmax(const float* __restrict__ a2, float* scal)
{
    int row = blockIdx.x, t = threadIdx.x;
    float v = a2[(size_t)row * Mm + t];
    __shared__ float red[256];
    red[t] = v; __syncthreads();
    for (int o = 128; o > 0; o >>= 1) { if (t < o) red[t] += red[t+o]; __syncthreads(); }
    if (t == 0) atomicMax((unsigned*)&scal[0], __float_as_uint(red[0]));
}

__global__ __launch_bounds__(256)
void k_colmax(const float* __restrict__ a2, float* scal)
{
    int bh = blockIdx.x, j = threadIdx.x;
    const float* p = a2 + ((size_t)bh << 16) + j;
    float s = 0.f;
    for (int i = 0; i < Mm; i++) s += p[(size_t)i * Mm];
    __shared__ float red[256];
    red[j] = s; __syncthreads();
    for (int o = 128; o > 0; o >>= 1) { if (j < o) red[j] = fmaxf(red[j], red[j+o]); __syncthreads(); }
    if (j == 0) atomicMax((unsigned*)&scal[1], __float_as_uint(red[0]));
}

__global__ __launch_bounds__(256)
void k_zinit(const float* __restrict__ a2, float* __restrict__ z, const float* scal)
{
    int g = blockIdx.x * 256 + threadIdx.x;
    float inv = 1.0f / (scal[0] * scal[1]);
    int j = g & 255, i = (g >> 8) & 255, bh = g >> 16;
    z[g] = a2[((size_t)bh << 16) + (size_t)j * Mm + i] * inv;
}

// ---------------------------------------------------------------------------
// Depthwise residual conv
// ---------------------------------------------------------------------------
__global__ __launch_bounds__(256)
void k_conv(const float* __restrict__ v, const float* __restrict__ rw,
            float* __restrict__ outg)
{
    int bh = blockIdx.y;
    int b = bh >> 3, h = bh & 7;
    int n0 = blockIdx.x * 64;
    __shared__ float vs[96][64];
    __shared__ float ws[KCONV];
    int t = threadIdx.x;
    const float* vp = v + (size_t)bh * Nn * DHd;
    for (int idx = t; idx < 96 * 64; idx += 256) {
        int r = idx >> 6, d = idx & 63;
        int n = n0 - 16 + r;
        vs[r][d] = (n >= 0 && n < Nn) ? vp[(size_t)n * DHd + d] : 0.0f;
    }
    if (t < KCONV) ws[t] = rw[h * KCONV + t];
    __syncthreads();
    int d = t & 63, r0 = t >> 6;
    for (int nn = r0; nn < 64; nn += 4) {
        float acc = 0.f;
        #pragma unroll
        for (int tt = 0; tt < KCONV; tt++)
            acc = fmaf(ws[tt], vs[nn + tt][d], acc);
        outg[((size_t)(b * Nn + n0 + nn)) * DIM + h * DHd + d] += acc;
    }
}

// ---------------------------------------------------------------------------
// Host-side launch helpers (4 tgemm instantiations)
// big   <128,128,64,64,F> : 4 warps / 128 threads, 16 FLOP/LDS-byte
// bigNT <128,128,64,64,T>
// n64   <128, 64,32,32,F> : 8 warps, N=64 shapes with large M
// small < 64, 64,32,16,F> : 8 warps, small-M N=64 shapes (a3v, w)
// ---------------------------------------------------------------------------
static inline void tg_big(const float* A, const float* B, const float* D, float* C,
                          int M, int N, int K, int lda, int ldb, int ldd, int ldc,
                          long long sA, long long sB, long long sD, long long sC,
                          int batch, float alpha, float beta, float diag,
                          int epi = 0, const float* e1 = nullptr, const float* e2 = nullptr,
                          float* e3 = nullptr, float* e4 = nullptr)
{
    tgemm<128,128,64,64,false><<<dim3(N/128, M/128, batch), 128>>>(
        A, B, D, C, K, lda, ldb, ldd, ldc, sA, sB, sD, sC,
        alpha, beta, diag, epi, e1, e2, e3, e4);
}
static inline void tg_bigNT(const float* A, const float* B, float* C,
                            int M, int N, int K, int lda, int ldb, int ldc,
                            long long sA, long long sB, long long sC, int batch)
{
    tgemm<128,128,64,64,true><<<dim3(N/128, M/128, batch), 128>>>(
        A, B, nullptr, C, K, lda, ldb, 0, ldc, sA, sB, 0, sC,
        1.f, 0.f, 0.f, 0, nullptr, nullptr, nullptr, nullptr);
}
static inline void tg_n64(const float* A, const float* B, float* C,
                          int M, int K, int lda, int ldb, int ldc,
                          long long sA, long long sB, long long sC,
                          int batch, int epi)
{
    tgemm<128,64,32,32,false><<<dim3(1, M/128, batch), 256>>>(
        A, B, nullptr, C, K, lda, ldb, 0, ldc, sA, sB, 0, sC,
        1.f, 0.f, 0.f, epi, nullptr, nullptr, nullptr, nullptr);
}
static inline void tg_small(const float* A, const float* B, float* C,
                            int M, int N, int K, int lda, int ldb, int ldc,
                            long long sA, long long sB, long long sC, int batch)
{
    tgemm<64,64,32,16,false><<<dim3(N/64, M/64, batch), 256>>>(
        A, B, nullptr, C, K, lda, ldb, 0, ldc, sA, sB, 0, sC,
        1.f, 0.f, 0.f, 0, nullptr, nullptr, nullptr, nullptr);
}

extern "C" void kernel_launch(void* const* d_in, const int* in_sizes, int n_in,
                              void* d_out, int out_size)
{
    const float* x      = (const float*)d_in[0];
    const float* norm_w = (const float*)d_in[1];
    const float* norm_b = (const float*)d_in[2];
    const float* w_qkv  = (const float*)d_in[3];
    const float* w_out  = (const float*)d_in[4];
    const float* b_out  = (const float*)d_in[5];
    const float* res_w  = (const float*)d_in[6];
    float* out = (float*)d_out;

    float* buf = nullptr;
    cudaGetSymbolAddress((void**)&buf, g_buf);

    float* xn   = buf + OFF_XN;
    float* q    = buf + OFF_Q;
    float* k    = buf + OFF_K;
    float* v    = buf + OFF_V;
    float* ql   = buf + OFF_QL;
    float* kl   = buf + OFF_KL;
    float* a1   = buf + OFF_A1;
    float* a3   = buf + OFF_A3;
    float* a2   = buf + OFF_A2;
    float* zA   = buf + OFF_ZA;
    float* zB   = buf + OFF_ZB;
    float* P    = buf + OFF_P;
    float* S    = buf + OFF_S;
    float* U    = buf + OFF_U;
    float* a3v  = buf + OFF_A3V;
    float* w    = buf + OFF_W;
    float* scal = buf + OFF_SCAL;
    float* outg = xn;   // reuse (xn dead after qkv GEMM); gathered [BN][DIM]

    const long long sQ = (long long)Nn * DHd, sL = (long long)Mm * DHd;
    const long long s2 = (long long)Mm * Mm;
    const long long sA1 = (long long)Nn * Mm;

    // 1. LayerNorm
    k_layernorm<<<BN, 128>>>(x, norm_w, norm_b, xn);

    // 2. qkv projection (wide tiles, scatter epilogue, q scale)
    tg_big(xn, w_qkv, nullptr, q, BN, 1536, DIM, DIM, 1536, 0, 0,
           0, 0, 0, 0, 1, 1.f, 0.f, 0.f, 1, nullptr, nullptr, k, v);

    // 3. landmarks
    k_landmark<<<(int)(SZ_L / 256), 256>>>(q, k, ql, kl);

    // 4. similarity GEMMs (NT, K=64)
    tg_bigNT(q,  kl, a1, Nn, Mm, DHd, DHd, DHd, Mm, sQ, sL, sA1, BH);
    tg_bigNT(ql, kl, a2, Mm, Mm, DHd, DHd, DHd, Mm, sL, sL, s2, BH);
    tg_bigNT(ql, k,  a3, Mm, Nn, DHd, DHd, DHd, Nn, sL, sQ, (long long)Mm * Nn, BH);

    // 5. softmaxes (in place)
    k_softmax256<<<BH * Nn / 8, 256>>>(a1);
    k_softmax256<<<BH * Mm / 8, 256>>>(a2);
    k_softmax4096<<<BH * Mm, 256>>>(a3);

    // 6. pinv init: z = a2^T / (max(rowsum) * max(colsum))
    k_reset_scal<<<1, 32>>>(scal);
    k_rowmax<<<BH * Mm, 256>>>(a2, scal);
    k_colmax<<<BH, 256>>>(a2, scal);
    k_zinit<<<(int)(SZ_A2 / 256), 256>>>(a2, zA, scal);

    // 7. Newton-Schulz (6 iters), batched 256^3, wide tiles (128 CTAs, 2/SM)
    float* zc = zA; float* zn = zB;
    for (int it = 0; it < 6; it++) {
        tg_big(a2, zc, nullptr, P, Mm, Mm, Mm, Mm, Mm, 0, Mm,
               s2, s2, 0, s2, BH, 1.f, 0.f, 0.f);
        tg_big(P, P, P, S, Mm, Mm, Mm, Mm, Mm, Mm, Mm,
               s2, s2, s2, s2, BH, 1.f, -7.f, 15.f);
        tg_big(P, S, nullptr, U, Mm, Mm, Mm, Mm, Mm, 0, Mm,
               s2, s2, 0, s2, BH, -1.f, 0.f, 13.f);
        tg_big(zc, U, nullptr, zn, Mm, Mm, Mm, Mm, Mm, 0, Mm,
               s2, s2, 0, s2, BH, 0.25f, 0.f, 0.f);
        float* tmp = zc; zc = zn; zn = tmp;
    }

    // 8. a3v = a3 @ v   [256 x 64, K=4096]
    tg_small(a3, v, a3v, Mm, DHd, Nn, Nn, DHd, DHd,
             (long long)Mm * Nn, sQ, sL, BH);

    // 9. w = z @ a3v    [256 x 64, K=256]  (associativity reorder: tiny GEMM)
    tg_small(zc, a3v, w, Mm, DHd, Mm, Mm, DHd, DHd,
             s2, sL, sL, BH);

    // 10. outg = gathered(a1 @ w)   [4096 x 64, K=256]  (epi 3 head-scatter)
    tg_n64(a1, w, outg, Nn, Mm, Mm, DHd, DIM,
           sA1, sL, 0, BH, 3);

    // 11. residual depthwise conv (adds into gathered layout)
    k_conv<<<dim3(Nn / 64, BH), 256>>>(v, res_w, outg);

    // 12. final: out = x + outg @ w_out + b_out   (epi 2)
    tg_big(outg, w_out, nullptr, out, BN, DIM, DIM, DIM, DIM, 0, DIM,
           0, 0, 0, 0, 1, 1.f, 0.f, 0.f, 2, b_out, x, nullptr, nullptr);
}